// round 9
// baseline (speedup 1.0000x reference)
#include <cuda_runtime.h>
#include <cuda_bf16.h>
#include <cstdint>

#define H    192
#define PP   64
#define LDT  132
#define TSTR 24
#define TILE_F (128 * TSTR)           // 3072 floats per A buffer

#define SA_BYTES   (2 * TILE_F * 4)   // 24576 B : A f32 double buffer
#define OFF_WB     SA_BYTES           // W packed region (bytes)
#define W_CHUNK_B  12288              // 128 rows * 3 splits * 4 pairs * 8 B
#define OFF_BIAS   (128 * LDT)        // float idx 16896 (Lg aliases tiles)
#define OFF_POS    (OFF_BIAS + 128)
#define SMEM_FLOATS (OFF_POS + 192)   // 17216 floats = 68864 B

#define MARGIN_TH  4e-4f

// pre-split W: [chunk 24][n 128][split 3][pair4][2 u32]
__device__ __align__(16) unsigned int g_wpk[73728];
__device__ int g_cnt;
__device__ int g_list[262144];

__global__ void reset_cnt() { if (threadIdx.x == 0) g_cnt = 0; }

static __device__ __forceinline__ float bf16v(float x) {
    return __bfloat162float(__float2bfloat16(x));
}
static __device__ unsigned int split_bits(float x, int s) {
    float h = bf16v(x);
    if (s == 0) return __float_as_uint(h) >> 16;
    float m = bf16v(x - h);
    if (s == 1) return __float_as_uint(m) >> 16;
    float l = bf16v((x - h) - m);
    return __float_as_uint(l) >> 16;
}

__global__ void prep_w(const float* __restrict__ Ws, const float* __restrict__ Wb) {
    int idx = blockIdx.x * blockDim.x + threadIdx.x;   // 0..36863
    if (idx >= 36864) return;
    int t  = idx & 3;
    int r3 = idx >> 2;
    int s  = r3 % 3;
    int nc = r3 / 3;
    int n  = nc & 127;
    int c  = nc >> 7;
    const float* row = (n < 64) ? (Ws + (size_t)n * 384) : (Wb + (size_t)(n - 64) * 384);
    int k0 = c * 16 + 2 * t;
    unsigned int p0 = (split_bits(row[k0 + 1], s) << 16) | split_bits(row[k0], s);
    unsigned int p1 = (split_bits(row[k0 + 9], s) << 16) | split_bits(row[k0 + 8], s);
    g_wpk[idx * 2]     = p0;
    g_wpk[idx * 2 + 1] = p1;
}

static __device__ __forceinline__ uint32_t s2u(const void* p) {
    uint32_t a;
    asm("{ .reg .u64 t; cvta.to.shared.u64 t, %1; cvt.u32.u64 %0, t; }" : "=r"(a) : "l"(p));
    return a;
}
static __device__ __forceinline__ void cpasync16(uint32_t s, const void* g) {
    asm volatile("cp.async.cg.shared.global [%0], [%1], 16;" :: "r"(s), "l"(g));
}
static __device__ __forceinline__ void split3(float x, float y,
                                              uint32_t& h, uint32_t& m, uint32_t& l) {
    asm("cvt.rn.bf16x2.f32 %0, %1, %2;" : "=r"(h) : "f"(y), "f"(x));
    float hx = __uint_as_float(h << 16);
    float hy = __uint_as_float(h & 0xFFFF0000u);
    float mx = x - hx, my = y - hy;
    asm("cvt.rn.bf16x2.f32 %0, %1, %2;" : "=r"(m) : "f"(my), "f"(mx));
    float nx = __uint_as_float(m << 16);
    float ny = __uint_as_float(m & 0xFFFF0000u);
    float lx = mx - nx, ly = my - ny;
    asm("cvt.rn.bf16x2.f32 %0, %1, %2;" : "=r"(l) : "f"(ly), "f"(lx));
}
static __device__ __forceinline__ void mma16816(float* d, const uint32_t* a, uint2 b) {
    asm volatile("mma.sync.aligned.m16n8k16.row.col.f32.bf16.bf16.f32 "
        "{%0,%1,%2,%3}, {%4,%5,%6,%7}, {%8,%9}, {%0,%1,%2,%3};"
        : "+f"(d[0]), "+f"(d[1]), "+f"(d[2]), "+f"(d[3])
        : "r"(a[0]), "r"(a[1]), "r"(a[2]), "r"(a[3]), "r"(b.x), "r"(b.y));
}

__global__ __launch_bounds__(256, 2)
void taps_mma(const float* __restrict__ token_state,
              const float* __restrict__ prev_state,
              const float* __restrict__ b_sel,
              const float* __restrict__ b_br,
              const float* __restrict__ patch_values,
              const float* __restrict__ patch_positions,
              float* __restrict__ out_ps,
              float* __restrict__ out_w,
              float* __restrict__ out_anchor,
              float* __restrict__ out_lm,
              float* __restrict__ out_bm,
              float* __restrict__ out_md,
              float* __restrict__ out_rad,
              float* __restrict__ out_bs,
              int B)
{
    extern __shared__ float smem[];
    float* sA   = smem;
    char*  smwc = (char*)smem + OFF_WB;
    float* Lg   = smem;
    float* bias = smem + OFF_BIAS;
    float* posx = smem + OFF_POS;
    float* posy = posx + 64;
    float* posz = posy + 64;

    const int tid  = threadIdx.x;
    const int wid  = tid >> 5;
    const int lane = tid & 31;
    const int m0   = blockIdx.x * 128;

    if (tid < 64) {
        bias[tid]      = b_sel[tid];
        bias[64 + tid] = b_br[tid];
        posx[tid] = patch_positions[tid * 3 + 0];
        posy[tid] = patch_positions[tid * 3 + 1];
        posz[tid] = patch_positions[tid * 3 + 2];
    }

    const uint32_t sAb = s2u(sA);
    const uint32_t sWb = s2u(smwc);
    const char* wsrc = (const char*)g_wpk;

    const int wm   = wid & 3;
    const int wn   = wid >> 2;
    const int roff = wm * 32;
    const int noff = wn * 64;
    const int g    = lane >> 2;
    const int t2   = lane & 3;

    float acc[2][8][4];
    #pragma unroll
    for (int mi = 0; mi < 2; mi++)
        #pragma unroll
        for (int j = 0; j < 8; j++)
            #pragma unroll
            for (int q = 0; q < 4; q++) acc[mi][j][q] = 0.0f;

    const int r_a = tid >> 2,         s_a = tid & 3;
    const int r_b = (tid + 256) >> 2, s_b = tid & 3;

    auto load_chunk = [&](int c, int buf) {
        const float* qs = (c < 12) ? token_state : prev_state;
        const int q0 = (c % 12) * 16;
        cpasync16(sAb + (uint32_t)(buf * TILE_F + r_a * TSTR + s_a * 4) * 4,
                  qs + (size_t)(m0 + r_a) * H + q0 + s_a * 4);
        cpasync16(sAb + (uint32_t)(buf * TILE_F + r_b * TSTR + s_b * 4) * 4,
                  qs + (size_t)(m0 + r_b) * H + q0 + s_b * 4);
        #pragma unroll
        for (int q = 0; q < 3; q++)
            cpasync16(sWb + buf * W_CHUNK_B + tid * 16 + q * 4096,
                      wsrc + (size_t)c * W_CHUNK_B + tid * 16 + q * 4096);
        asm volatile("cp.async.commit_group;");
    };

    load_chunk(0, 0);

    for (int c = 0; c < 24; c++) {
        const int buf = c & 1;
        if (c < 23) {
            load_chunk(c + 1, buf ^ 1);
            asm volatile("cp.async.wait_group 1;");
        } else {
            asm volatile("cp.async.wait_group 0;");
        }
        __syncthreads();

        uint32_t Ah[2][4], Am[2][4], Al[2][4];
        #pragma unroll
        for (int mi = 0; mi < 2; mi++) {
            const float* a0p = sA + buf * TILE_F + (roff + mi * 16 + g) * TSTR + 2 * t2;
            const float* a1p = a0p + 8 * TSTR;
            float2 q00 = *(const float2*)a0p;
            float2 q10 = *(const float2*)a1p;
            float2 q01 = *(const float2*)(a0p + 8);
            float2 q11 = *(const float2*)(a1p + 8);
            split3(q00.x, q00.y, Ah[mi][0], Am[mi][0], Al[mi][0]);
            split3(q10.x, q10.y, Ah[mi][1], Am[mi][1], Al[mi][1]);
            split3(q01.x, q01.y, Ah[mi][2], Am[mi][2], Al[mi][2]);
            split3(q11.x, q11.y, Ah[mi][3], Am[mi][3], Al[mi][3]);
        }

        const char* wb = smwc + buf * W_CHUNK_B;
        #pragma unroll
        for (int j = 0; j < 8; j++) {
            const int n = noff + j * 8 + g;
            uint2 bh = *(const uint2*)(wb + ((n * 3 + 0) * 4 + t2) * 8);
            uint2 bm = *(const uint2*)(wb + ((n * 3 + 1) * 4 + t2) * 8);
            uint2 bl = *(const uint2*)(wb + ((n * 3 + 2) * 4 + t2) * 8);
            #pragma unroll
            for (int mi = 0; mi < 2; mi++) {
                mma16816(acc[mi][j], Ah[mi], bh);
                mma16816(acc[mi][j], Ah[mi], bm);
                mma16816(acc[mi][j], Am[mi], bh);
                mma16816(acc[mi][j], Ah[mi], bl);
                mma16816(acc[mi][j], Al[mi], bh);
                mma16816(acc[mi][j], Am[mi], bm);
            }
        }
        __syncthreads();
    }

    #pragma unroll
    for (int mi = 0; mi < 2; mi++) {
        const int r0 = roff + mi * 16 + g;
        #pragma unroll
        for (int j = 0; j < 8; j++) {
            const int cb = noff + j * 8 + 2 * t2;
            float2 v0 = {acc[mi][j][0] + bias[cb], acc[mi][j][1] + bias[cb + 1]};
            float2 v1 = {acc[mi][j][2] + bias[cb], acc[mi][j][3] + bias[cb + 1]};
            *(float2*)&Lg[r0 * LDT + cb]       = v0;
            *(float2*)&Lg[(r0 + 8) * LDT + cb] = v1;
        }
    }
    __syncthreads();

    // ---- postprocess + margin flagging ----
    const unsigned F = 0xffffffffu;
    const float PXa = posx[lane],      PYa = posy[lane],      PZa = posz[lane];
    const float PXb = posx[lane + 32], PYb = posy[lane + 32], PZb = posz[lane + 32];
    const float RAD  = 0.42f;
    const float NEGK = -1.0f / (2.0f * 0.42f * 0.42f);

    for (int r = 0; r < 16; r++) {
        int t  = wid * 16 + r;
        int tg = m0 + t;
        if (tg >= B) break;
        const float* L = &Lg[t * LDT];
        float ba = L[lane],      bb = L[lane + 32];
        float ga = L[lane + 64], gb = L[lane + 96];

        float mx = fmaxf(ba, bb);
        #pragma unroll
        for (int o = 16; o; o >>= 1) mx = fmaxf(mx, __shfl_xor_sync(F, mx, o));
        float ea = expf(ba - mx), eb = expf(bb - mx);
        float s = ea + eb;
        #pragma unroll
        for (int o = 16; o; o >>= 1) s += __shfl_xor_sync(F, s, o);
        float inv = 1.0f / s;
        float wa = ea * inv, wb = eb * inv;

        float ax = wa * PXa + wb * PXb;
        float ay = wa * PYa + wb * PYb;
        float az = wa * PZa + wb * PZb;
        #pragma unroll
        for (int o = 16; o; o >>= 1) {
            ax += __shfl_xor_sync(F, ax, o);
            ay += __shfl_xor_sync(F, ay, o);
            az += __shfl_xor_sync(F, az, o);
        }

        float dxa = ax - PXa, dya = ay - PYa, dza = az - PZa;
        float dxb = ax - PXb, dyb = ay - PYb, dzb = az - PZb;
        float da = sqrtf(dxa * dxa + dya * dya + dza * dza);
        float db = sqrtf(dxb * dxb + dyb * dyb + dzb * dzb);
        float ka = expf(da * da * NEGK);
        float kb = expf(db * db * NEGK);
        bool la = (da <= RAD), lb = (db <= RAD);

        unsigned long long keya = (((unsigned long long)__float_as_uint(da)) << 32) | (unsigned)lane;
        unsigned long long keyb = (((unsigned long long)__float_as_uint(db)) << 32) | (unsigned)(lane + 32);
        unsigned long long kmin = keya < keyb ? keya : keyb;
        #pragma unroll
        for (int o = 16; o; o >>= 1) {
            unsigned long long ok = __shfl_xor_sync(F, kmin, o);
            if (ok < kmin) kmin = ok;
        }
        int nearest = (int)(kmin & 0x3fu);
        float dmin = __uint_as_float((unsigned)(kmin >> 32));
        la = la || (lane == nearest);
        lb = lb || (lane + 32 == nearest);

        float va_ = la ? -1e9f : ga;
        float vb_ = lb ? -1e9f : gb;
        float tv[6]; int ti[6];
        #pragma unroll
        for (int j = 0; j < 6; j++) {
            float bv; int bi;
            if (va_ >= vb_) { bv = va_; bi = lane; } else { bv = vb_; bi = lane + 32; }
            #pragma unroll
            for (int o = 16; o; o >>= 1) {
                float ov = __shfl_xor_sync(F, bv, o);
                int   oi = __shfl_xor_sync(F, bi, o);
                if (ov > bv || (ov == bv && oi < bi)) { bv = ov; bi = oi; }
            }
            tv[j] = bv; ti[j] = bi;
            if (bi == lane)      va_ = -3.4e38f;
            if (bi == lane + 32) vb_ = -3.4e38f;
        }
        // 7th-best value (for top-k margin)
        float v7 = fmaxf(va_, vb_);
        // margins: radius-boundary, argmin gap
        float mr = fminf(fabsf(da - RAD), fabsf(db - RAD));
        float c1 = (lane == nearest)      ? 3.4e38f : da;
        float c2 = (lane + 32 == nearest) ? 3.4e38f : db;
        float d2 = fminf(c1, c2);
        #pragma unroll
        for (int o = 16; o; o >>= 1) {
            v7 = fmaxf(v7, __shfl_xor_sync(F, v7, o));
            mr = fminf(mr, __shfl_xor_sync(F, mr, o));
            d2 = fminf(d2, __shfl_xor_sync(F, d2, o));
        }
        if (lane == 0) {
            float mm = fminf(tv[5] - v7, fminf(mr, d2 - dmin));
            if (mm < MARGIN_TH) {
                int slot = atomicAdd(&g_cnt, 1);
                g_list[slot] = tg;
            }
        }

        float s6 = 0.0f, e6[6];
        #pragma unroll
        for (int j = 0; j < 6; j++) { e6[j] = expf(tv[j] - tv[0]); s6 += e6[j]; }
        float is6 = 1.0f / s6;
        float sba = 0.0f, sbb = 0.0f;
        #pragma unroll
        for (int j = 0; j < 6; j++) {
            float v = e6[j] * is6;
            if (ti[j] == lane)      sba = v;
            if (ti[j] == lane + 32) sbb = v;
        }

        float fla = la ? 1.0f : 0.0f, flb = lb ? 1.0f : 0.0f;
        float ma = wa * ka * fla + 0.18f * sba;
        float mb = wb * kb * flb + 0.18f * sbb;
        float smx = ma + mb;
        #pragma unroll
        for (int o = 16; o; o >>= 1) smx += __shfl_xor_sync(F, smx, o);
        float invd = 1.0f / fmaxf(smx, 1e-6f);
        float Wa = ma * invd, Wb = mb * invd;

        out_w[(size_t)tg * PP + lane]      = Wa;
        out_w[(size_t)tg * PP + 32 + lane] = Wb;

        float lm = Wa * fla + Wb * flb;
        float bm = Wa * (1.0f - fla) + Wb * (1.0f - flb);
        float md = Wa * da + Wb * db;
        #pragma unroll
        for (int o = 16; o; o >>= 1) {
            lm += __shfl_xor_sync(F, lm, o);
            bm += __shfl_xor_sync(F, bm, o);
            md += __shfl_xor_sync(F, md, o);
        }

        float pacc[6] = {0, 0, 0, 0, 0, 0};
        unsigned bal0 = __ballot_sync(F, Wa != 0.0f);
        unsigned bal1 = __ballot_sync(F, Wb != 0.0f);
        while (bal0) {
            int p = __ffs(bal0) - 1; bal0 &= bal0 - 1;
            float wv = __shfl_sync(F, Wa, p);
            const float* row = patch_values + p * H;
            #pragma unroll
            for (int j = 0; j < 6; j++) pacc[j] += wv * __ldg(row + lane + 32 * j);
        }
        while (bal1) {
            int p = __ffs(bal1) - 1; bal1 &= bal1 - 1;
            float wv = __shfl_sync(F, Wb, p);
            const float* row = patch_values + (p + 32) * H;
            #pragma unroll
            for (int j = 0; j < 6; j++) pacc[j] += wv * __ldg(row + lane + 32 * j);
        }
        #pragma unroll
        for (int j = 0; j < 6; j++) out_ps[(size_t)tg * H + lane + 32 * j] = pacc[j];

        if (lane == 0) {
            out_anchor[(size_t)tg * 3 + 0] = ax;
            out_anchor[(size_t)tg * 3 + 1] = ay;
            out_anchor[(size_t)tg * 3 + 2] = az;
            out_lm[tg]  = lm;
            out_bm[tg]  = bm;
            out_md[tg]  = md;
            out_rad[tg] = RAD;
            out_bs[tg]  = 0.18f;
        }
    }
}

// ---- pass 2: recompute flagged tokens with EXACT R2 fp32 math ----
__global__ __launch_bounds__(256)
void fixup(const float* __restrict__ token_state,
           const float* __restrict__ prev_state,
           const float* __restrict__ W_sel,
           const float* __restrict__ b_sel,
           const float* __restrict__ W_br,
           const float* __restrict__ b_br,
           const float* __restrict__ patch_values,
           const float* __restrict__ patch_positions,
           float* __restrict__ out_ps,
           float* __restrict__ out_w,
           float* __restrict__ out_anchor,
           float* __restrict__ out_lm,
           float* __restrict__ out_bm,
           float* __restrict__ out_md,
           float* __restrict__ out_rad,
           float* __restrict__ out_bs)
{
    const unsigned F = 0xffffffffu;
    const int lane  = threadIdx.x & 31;
    const int warpG = (blockIdx.x * blockDim.x + threadIdx.x) >> 5;
    const int nwarp = (gridDim.x * blockDim.x) >> 5;
    const int n = g_cnt;

    const float PXa = __ldg(&patch_positions[lane * 3 + 0]);
    const float PYa = __ldg(&patch_positions[lane * 3 + 1]);
    const float PZa = __ldg(&patch_positions[lane * 3 + 2]);
    const float PXb = __ldg(&patch_positions[(lane + 32) * 3 + 0]);
    const float PYb = __ldg(&patch_positions[(lane + 32) * 3 + 1]);
    const float PZb = __ldg(&patch_positions[(lane + 32) * 3 + 2]);
    const float RAD  = 0.42f;
    const float NEGK = -1.0f / (2.0f * 0.42f * 0.42f);

    for (int i = warpG; i < n; i += nwarp) {
        const int tg = g_list[i];
        const float* q1 = token_state + (size_t)tg * H;
        const float* q2 = prev_state + (size_t)tg * H;
        const float* w0 = W_sel + (size_t)lane * 384;
        const float* w1 = W_sel + (size_t)(lane + 32) * 384;
        const float* w2 = W_br + (size_t)lane * 384;
        const float* w3 = W_br + (size_t)(lane + 32) * 384;

        // exact R2 order: single fmaf chain, k = 0..383 ascending, then +bias
        float a0 = 0.f, a1 = 0.f, a2 = 0.f, a3 = 0.f;
        #pragma unroll 8
        for (int k = 0; k < 192; k++) {
            float q = __ldg(q1 + k);
            a0 = fmaf(q, __ldg(w0 + k), a0);
            a1 = fmaf(q, __ldg(w1 + k), a1);
            a2 = fmaf(q, __ldg(w2 + k), a2);
            a3 = fmaf(q, __ldg(w3 + k), a3);
        }
        #pragma unroll 8
        for (int k = 0; k < 192; k++) {
            float q = __ldg(q2 + k);
            a0 = fmaf(q, __ldg(w0 + 192 + k), a0);
            a1 = fmaf(q, __ldg(w1 + 192 + k), a1);
            a2 = fmaf(q, __ldg(w2 + 192 + k), a2);
            a3 = fmaf(q, __ldg(w3 + 192 + k), a3);
        }
        float ba = a0 + __ldg(b_sel + lane);
        float bb = a1 + __ldg(b_sel + lane + 32);
        float ga = a2 + __ldg(b_br + lane);
        float gb = a3 + __ldg(b_br + lane + 32);

        // ---- identical postprocess ----
        float mx = fmaxf(ba, bb);
        #pragma unroll
        for (int o = 16; o; o >>= 1) mx = fmaxf(mx, __shfl_xor_sync(F, mx, o));
        float ea = expf(ba - mx), eb = expf(bb - mx);
        float s = ea + eb;
        #pragma unroll
        for (int o = 16; o; o >>= 1) s += __shfl_xor_sync(F, s, o);
        float inv = 1.0f / s;
        float wa = ea * inv, wb = eb * inv;

        float ax = wa * PXa + wb * PXb;
        float ay = wa * PYa + wb * PYb;
        float az = wa * PZa + wb * PZb;
        #pragma unroll
        for (int o = 16; o; o >>= 1) {
            ax += __shfl_xor_sync(F, ax, o);
            ay += __shfl_xor_sync(F, ay, o);
            az += __shfl_xor_sync(F, az, o);
        }

        float dxa = ax - PXa, dya = ay - PYa, dza = az - PZa;
        float dxb = ax - PXb, dyb = ay - PYb, dzb = az - PZb;
        float da = sqrtf(dxa * dxa + dya * dya + dza * dza);
        float db = sqrtf(dxb * dxb + dyb * dyb + dzb * dzb);
        float ka = expf(da * da * NEGK);
        float kb = expf(db * db * NEGK);
        bool la = (da <= RAD), lb = (db <= RAD);

        unsigned long long keya = (((unsigned long long)__float_as_uint(da)) << 32) | (unsigned)lane;
        unsigned long long keyb = (((unsigned long long)__float_as_uint(db)) << 32) | (unsigned)(lane + 32);
        unsigned long long kmin = keya < keyb ? keya : keyb;
        #pragma unroll
        for (int o = 16; o; o >>= 1) {
            unsigned long long ok = __shfl_xor_sync(F, kmin, o);
            if (ok < kmin) kmin = ok;
        }
        int nearest = (int)(kmin & 0x3fu);
        la = la || (lane == nearest);
        lb = lb || (lane + 32 == nearest);

        float va_ = la ? -1e9f : ga;
        float vb_ = lb ? -1e9f : gb;
        float tv[6]; int ti[6];
        #pragma unroll
        for (int j = 0; j < 6; j++) {
            float bv; int bi;
            if (va_ >= vb_) { bv = va_; bi = lane; } else { bv = vb_; bi = lane + 32; }
            #pragma unroll
            for (int o = 16; o; o >>= 1) {
                float ov = __shfl_xor_sync(F, bv, o);
                int   oi = __shfl_xor_sync(F, bi, o);
                if (ov > bv || (ov == bv && oi < bi)) { bv = ov; bi = oi; }
            }
            tv[j] = bv; ti[j] = bi;
            if (bi == lane)      va_ = -3.4e38f;
            if (bi == lane + 32) vb_ = -3.4e38f;
        }
        float s6 = 0.0f, e6[6];
        #pragma unroll
        for (int j = 0; j < 6; j++) { e6[j] = expf(tv[j] - tv[0]); s6 += e6[j]; }
        float is6 = 1.0f / s6;
        float sba = 0.0f, sbb = 0.0f;
        #pragma unroll
        for (int j = 0; j < 6; j++) {
            float v = e6[j] * is6;
            if (ti[j] == lane)      sba = v;
            if (ti[j] == lane + 32) sbb = v;
        }

        float fla = la ? 1.0f : 0.0f, flb = lb ? 1.0f : 0.0f;
        float ma = wa * ka * fla + 0.18f * sba;
        float mb = wb * kb * flb + 0.18f * sbb;
        float smx = ma + mb;
        #pragma unroll
        for (int o = 16; o; o >>= 1) smx += __shfl_xor_sync(F, smx, o);
        float invd = 1.0f / fmaxf(smx, 1e-6f);
        float Wa = ma * invd, Wb = mb * invd;

        out_w[(size_t)tg * PP + lane]      = Wa;
        out_w[(size_t)tg * PP + 32 + lane] = Wb;

        float lm = Wa * fla + Wb * flb;
        float bm = Wa * (1.0f - fla) + Wb * (1.0f - flb);
        float md = Wa * da + Wb * db;
        #pragma unroll
        for (int o = 16; o; o >>= 1) {
            lm += __shfl_xor_sync(F, lm, o);
            bm += __shfl_xor_sync(F, bm, o);
            md += __shfl_xor_sync(F, md, o);
        }

        float pacc[6] = {0, 0, 0, 0, 0, 0};
        unsigned bal0 = __ballot_sync(F, Wa != 0.0f);
        unsigned bal1 = __ballot_sync(F, Wb != 0.0f);
        while (bal0) {
            int p = __ffs(bal0) - 1; bal0 &= bal0 - 1;
            float wv = __shfl_sync(F, Wa, p);
            const float* row = patch_values + p * H;
            #pragma unroll
            for (int j = 0; j < 6; j++) pacc[j] += wv * __ldg(row + lane + 32 * j);
        }
        while (bal1) {
            int p = __ffs(bal1) - 1; bal1 &= bal1 - 1;
            float wv = __shfl_sync(F, Wb, p);
            const float* row = patch_values + (p + 32) * H;
            #pragma unroll
            for (int j = 0; j < 6; j++) pacc[j] += wv * __ldg(row + lane + 32 * j);
        }
        #pragma unroll
        for (int j = 0; j < 6; j++) out_ps[(size_t)tg * H + lane + 32 * j] = pacc[j];

        if (lane == 0) {
            out_anchor[(size_t)tg * 3 + 0] = ax;
            out_anchor[(size_t)tg * 3 + 1] = ay;
            out_anchor[(size_t)tg * 3 + 2] = az;
            out_lm[tg]  = lm;
            out_bm[tg]  = bm;
            out_md[tg]  = md;
            out_rad[tg] = RAD;
            out_bs[tg]  = 0.18f;
        }
    }
}

extern "C" void kernel_launch(void* const* d_in, const int* in_sizes, int n_in,
                              void* d_out, int out_size)
{
    const float* token_state     = (const float*)d_in[0];
    const float* prev_state      = (const float*)d_in[1];
    const float* W_sel           = (const float*)d_in[2];
    const float* b_sel           = (const float*)d_in[3];
    const float* W_br            = (const float*)d_in[4];
    const float* b_br            = (const float*)d_in[5];
    const float* patch_values    = (const float*)d_in[6];
    const float* patch_positions = (const float*)d_in[7];

    const int B = in_sizes[0] / H;
    float* o = (float*)d_out;
    float* out_ps     = o;
    float* out_w      = o + (size_t)B * H;
    float* out_anchor = o + (size_t)B * (H + PP);
    float* out_lm     = o + (size_t)B * (H + PP + 3);
    float* out_bm     = out_lm + B;
    float* out_md     = out_bm + B;
    float* out_rad    = out_md + B;
    float* out_bs     = out_rad + B;

    reset_cnt<<<1, 32>>>();
    prep_w<<<144, 256>>>(W_sel, W_br);

    const int smem_bytes = SMEM_FLOATS * sizeof(float); // 68864
    cudaFuncSetAttribute(taps_mma, cudaFuncAttributeMaxDynamicSharedMemorySize, smem_bytes);

    int grid = (B + 127) / 128;
    taps_mma<<<grid, 256, smem_bytes>>>(
        token_state, prev_state, b_sel, b_br,
        patch_values, patch_positions,
        out_ps, out_w, out_anchor, out_lm, out_bm, out_md, out_rad, out_bs, B);

    fixup<<<256, 256>>>(token_state, prev_state, W_sel, b_sel, W_br, b_br,
                        patch_values, patch_positions,
                        out_ps, out_w, out_anchor, out_lm, out_bm, out_md,
                        out_rad, out_bs);
}

// round 10
// speedup vs baseline: 1.9215x; 1.9215x over previous
#include <cuda_runtime.h>
#include <cuda_bf16.h>
#include <cstdint>

#define H    192
#define PP   64
#define LDT  132
#define TSTR 24
#define TILE_F (128 * TSTR)           // 3072 floats per A buffer

#define SA_BYTES   (2 * TILE_F * 4)   // 24576 B : A f32 double buffer
#define OFF_WB     SA_BYTES           // W packed region (bytes)
#define W_CHUNK_B  8192               // 128 rows * 2 splits * 4 pairs * 8 B
#define OFF_BIAS   (128 * LDT)        // float idx 16896 (Lg aliases tiles)
#define OFF_POS    (OFF_BIAS + 128)
#define SMEM_FLOATS (OFF_POS + 192)   // 17216 floats = 68864 B

#define MARGIN_TH  1e-4f

// pre-split W: [chunk 24][n 128][split 2][pair4][2 u32]
__device__ __align__(16) unsigned int g_wpk[49152];
__device__ int g_cnt;
__device__ int g_list[262144];

__global__ void reset_cnt() { if (threadIdx.x == 0) g_cnt = 0; }

static __device__ __forceinline__ float bf16v(float x) {
    return __bfloat162float(__float2bfloat16(x));
}
static __device__ unsigned int split_bits(float x, int s) {
    float h = bf16v(x);
    if (s == 0) return __float_as_uint(h) >> 16;
    float l = bf16v(x - h);
    return __float_as_uint(l) >> 16;
}

__global__ void prep_w(const float* __restrict__ Ws, const float* __restrict__ Wb) {
    int idx = blockIdx.x * blockDim.x + threadIdx.x;   // 0..24575
    if (idx >= 24576) return;
    int t  = idx & 3;
    int r3 = idx >> 2;
    int s  = r3 & 1;
    int nc = r3 >> 1;
    int n  = nc & 127;
    int c  = nc >> 7;
    const float* row = (n < 64) ? (Ws + (size_t)n * 384) : (Wb + (size_t)(n - 64) * 384);
    int k0 = c * 16 + 2 * t;
    unsigned int p0 = (split_bits(row[k0 + 1], s) << 16) | split_bits(row[k0], s);
    unsigned int p1 = (split_bits(row[k0 + 9], s) << 16) | split_bits(row[k0 + 8], s);
    g_wpk[idx * 2]     = p0;
    g_wpk[idx * 2 + 1] = p1;
}

static __device__ __forceinline__ uint32_t s2u(const void* p) {
    uint32_t a;
    asm("{ .reg .u64 t; cvta.to.shared.u64 t, %1; cvt.u32.u64 %0, t; }" : "=r"(a) : "l"(p));
    return a;
}
static __device__ __forceinline__ void cpasync16(uint32_t s, const void* g) {
    asm volatile("cp.async.cg.shared.global [%0], [%1], 16;" :: "r"(s), "l"(g));
}
static __device__ __forceinline__ void split2b(float x, float y, uint32_t& h, uint32_t& l) {
    asm("cvt.rn.bf16x2.f32 %0, %1, %2;" : "=r"(h) : "f"(y), "f"(x));
    float hx = __uint_as_float(h << 16);
    float hy = __uint_as_float(h & 0xFFFF0000u);
    float lx = x - hx, ly = y - hy;
    asm("cvt.rn.bf16x2.f32 %0, %1, %2;" : "=r"(l) : "f"(ly), "f"(lx));
}
static __device__ __forceinline__ void mma16816(float* d, const uint32_t* a, uint2 b) {
    asm volatile("mma.sync.aligned.m16n8k16.row.col.f32.bf16.bf16.f32 "
        "{%0,%1,%2,%3}, {%4,%5,%6,%7}, {%8,%9}, {%0,%1,%2,%3};"
        : "+f"(d[0]), "+f"(d[1]), "+f"(d[2]), "+f"(d[3])
        : "r"(a[0]), "r"(a[1]), "r"(a[2]), "r"(a[3]), "r"(b.x), "r"(b.y));
}

__global__ __launch_bounds__(256, 2)
void taps_mma(const float* __restrict__ token_state,
              const float* __restrict__ prev_state,
              const float* __restrict__ b_sel,
              const float* __restrict__ b_br,
              const float* __restrict__ patch_values,
              const float* __restrict__ patch_positions,
              float* __restrict__ out_ps,
              float* __restrict__ out_w,
              float* __restrict__ out_anchor,
              float* __restrict__ out_lm,
              float* __restrict__ out_bm,
              float* __restrict__ out_md,
              float* __restrict__ out_rad,
              float* __restrict__ out_bs,
              int B)
{
    extern __shared__ float smem[];
    float* sA   = smem;
    char*  smwc = (char*)smem + OFF_WB;
    float* Lg   = smem;
    float* bias = smem + OFF_BIAS;
    float* posx = smem + OFF_POS;
    float* posy = posx + 64;
    float* posz = posy + 64;

    const int tid  = threadIdx.x;
    const int wid  = tid >> 5;
    const int lane = tid & 31;
    const int m0   = blockIdx.x * 128;

    if (tid < 64) {
        bias[tid]      = b_sel[tid];
        bias[64 + tid] = b_br[tid];
        posx[tid] = patch_positions[tid * 3 + 0];
        posy[tid] = patch_positions[tid * 3 + 1];
        posz[tid] = patch_positions[tid * 3 + 2];
    }

    const uint32_t sAb = s2u(sA);
    const uint32_t sWb = s2u(smwc);
    const char* wsrc = (const char*)g_wpk;

    const int wm   = wid & 3;
    const int wn   = wid >> 2;
    const int roff = wm * 32;
    const int noff = wn * 64;
    const int g    = lane >> 2;
    const int t2   = lane & 3;

    float acc[2][8][4];
    #pragma unroll
    for (int mi = 0; mi < 2; mi++)
        #pragma unroll
        for (int j = 0; j < 8; j++)
            #pragma unroll
            for (int q = 0; q < 4; q++) acc[mi][j][q] = 0.0f;

    const int r_a = tid >> 2,         s_a = tid & 3;
    const int r_b = (tid + 256) >> 2, s_b = tid & 3;

    auto load_chunk = [&](int c, int buf) {
        const float* qs = (c < 12) ? token_state : prev_state;
        const int q0 = (c % 12) * 16;
        cpasync16(sAb + (uint32_t)(buf * TILE_F + r_a * TSTR + s_a * 4) * 4,
                  qs + (size_t)(m0 + r_a) * H + q0 + s_a * 4);
        cpasync16(sAb + (uint32_t)(buf * TILE_F + r_b * TSTR + s_b * 4) * 4,
                  qs + (size_t)(m0 + r_b) * H + q0 + s_b * 4);
        #pragma unroll
        for (int q = 0; q < 2; q++)
            cpasync16(sWb + buf * W_CHUNK_B + tid * 16 + q * 4096,
                      wsrc + (size_t)c * W_CHUNK_B + tid * 16 + q * 4096);
        asm volatile("cp.async.commit_group;");
    };

    load_chunk(0, 0);

    for (int c = 0; c < 24; c++) {
        const int buf = c & 1;
        if (c < 23) {
            load_chunk(c + 1, buf ^ 1);
            asm volatile("cp.async.wait_group 1;");
        } else {
            asm volatile("cp.async.wait_group 0;");
        }
        __syncthreads();

        uint32_t Ah[2][4], Al[2][4];
        #pragma unroll
        for (int mi = 0; mi < 2; mi++) {
            const float* a0p = sA + buf * TILE_F + (roff + mi * 16 + g) * TSTR + 2 * t2;
            const float* a1p = a0p + 8 * TSTR;
            float2 q00 = *(const float2*)a0p;
            float2 q10 = *(const float2*)a1p;
            float2 q01 = *(const float2*)(a0p + 8);
            float2 q11 = *(const float2*)(a1p + 8);
            split2b(q00.x, q00.y, Ah[mi][0], Al[mi][0]);
            split2b(q10.x, q10.y, Ah[mi][1], Al[mi][1]);
            split2b(q01.x, q01.y, Ah[mi][2], Al[mi][2]);
            split2b(q11.x, q11.y, Ah[mi][3], Al[mi][3]);
        }

        const char* wb = smwc + buf * W_CHUNK_B;
        #pragma unroll
        for (int j = 0; j < 8; j++) {
            const int n = noff + j * 8 + g;
            uint2 bh = *(const uint2*)(wb + ((n * 2 + 0) * 4 + t2) * 8);
            uint2 bl = *(const uint2*)(wb + ((n * 2 + 1) * 4 + t2) * 8);
            #pragma unroll
            for (int mi = 0; mi < 2; mi++) {
                mma16816(acc[mi][j], Ah[mi], bh);
                mma16816(acc[mi][j], Ah[mi], bl);
                mma16816(acc[mi][j], Al[mi], bh);
            }
        }
        __syncthreads();
    }

    #pragma unroll
    for (int mi = 0; mi < 2; mi++) {
        const int r0 = roff + mi * 16 + g;
        #pragma unroll
        for (int j = 0; j < 8; j++) {
            const int cb = noff + j * 8 + 2 * t2;
            float2 v0 = {acc[mi][j][0] + bias[cb], acc[mi][j][1] + bias[cb + 1]};
            float2 v1 = {acc[mi][j][2] + bias[cb], acc[mi][j][3] + bias[cb + 1]};
            *(float2*)&Lg[r0 * LDT + cb]       = v0;
            *(float2*)&Lg[(r0 + 8) * LDT + cb] = v1;
        }
    }
    __syncthreads();

    // ---- postprocess + margin flagging ----
    const unsigned F = 0xffffffffu;
    const float PXa = posx[lane],      PYa = posy[lane],      PZa = posz[lane];
    const float PXb = posx[lane + 32], PYb = posy[lane + 32], PZb = posz[lane + 32];
    const float RAD  = 0.42f;
    const float NEGK = -1.0f / (2.0f * 0.42f * 0.42f);

    for (int r = 0; r < 16; r++) {
        int t  = wid * 16 + r;
        int tg = m0 + t;
        if (tg >= B) break;
        const float* L = &Lg[t * LDT];
        float ba = L[lane],      bb = L[lane + 32];
        float ga = L[lane + 64], gb = L[lane + 96];

        float mx = fmaxf(ba, bb);
        #pragma unroll
        for (int o = 16; o; o >>= 1) mx = fmaxf(mx, __shfl_xor_sync(F, mx, o));
        float ea = expf(ba - mx), eb = expf(bb - mx);
        float s = ea + eb;
        #pragma unroll
        for (int o = 16; o; o >>= 1) s += __shfl_xor_sync(F, s, o);
        float inv = 1.0f / s;
        float wa = ea * inv, wb = eb * inv;

        float ax = wa * PXa + wb * PXb;
        float ay = wa * PYa + wb * PYb;
        float az = wa * PZa + wb * PZb;
        #pragma unroll
        for (int o = 16; o; o >>= 1) {
            ax += __shfl_xor_sync(F, ax, o);
            ay += __shfl_xor_sync(F, ay, o);
            az += __shfl_xor_sync(F, az, o);
        }

        float dxa = ax - PXa, dya = ay - PYa, dza = az - PZa;
        float dxb = ax - PXb, dyb = ay - PYb, dzb = az - PZb;
        float da = sqrtf(dxa * dxa + dya * dya + dza * dza);
        float db = sqrtf(dxb * dxb + dyb * dyb + dzb * dzb);
        float ka = expf(da * da * NEGK);
        float kb = expf(db * db * NEGK);
        bool la = (da <= RAD), lb = (db <= RAD);

        unsigned long long keya = (((unsigned long long)__float_as_uint(da)) << 32) | (unsigned)lane;
        unsigned long long keyb = (((unsigned long long)__float_as_uint(db)) << 32) | (unsigned)(lane + 32);
        unsigned long long kmin = keya < keyb ? keya : keyb;
        #pragma unroll
        for (int o = 16; o; o >>= 1) {
            unsigned long long ok = __shfl_xor_sync(F, kmin, o);
            if (ok < kmin) kmin = ok;
        }
        int nearest = (int)(kmin & 0x3fu);
        float dmin = __uint_as_float((unsigned)(kmin >> 32));
        la = la || (lane == nearest);
        lb = lb || (lane + 32 == nearest);

        float va_ = la ? -1e9f : ga;
        float vb_ = lb ? -1e9f : gb;
        float tv[6]; int ti[6];
        #pragma unroll
        for (int j = 0; j < 6; j++) {
            float bv; int bi;
            if (va_ >= vb_) { bv = va_; bi = lane; } else { bv = vb_; bi = lane + 32; }
            #pragma unroll
            for (int o = 16; o; o >>= 1) {
                float ov = __shfl_xor_sync(F, bv, o);
                int   oi = __shfl_xor_sync(F, bi, o);
                if (ov > bv || (ov == bv && oi < bi)) { bv = ov; bi = oi; }
            }
            tv[j] = bv; ti[j] = bi;
            if (bi == lane)      va_ = -3.4e38f;
            if (bi == lane + 32) vb_ = -3.4e38f;
        }
        float v7 = fmaxf(va_, vb_);
        float mr = fminf(fabsf(da - RAD), fabsf(db - RAD));
        float c1 = (lane == nearest)      ? 3.4e38f : da;
        float c2 = (lane + 32 == nearest) ? 3.4e38f : db;
        float d2 = fminf(c1, c2);
        #pragma unroll
        for (int o = 16; o; o >>= 1) {
            v7 = fmaxf(v7, __shfl_xor_sync(F, v7, o));
            mr = fminf(mr, __shfl_xor_sync(F, mr, o));
            d2 = fminf(d2, __shfl_xor_sync(F, d2, o));
        }
        if (lane == 0) {
            float mm = fminf(tv[5] - v7, fminf(mr, d2 - dmin));
            if (mm < MARGIN_TH) {
                int slot = atomicAdd(&g_cnt, 1);
                g_list[slot] = tg;
            }
        }

        float s6 = 0.0f, e6[6];
        #pragma unroll
        for (int j = 0; j < 6; j++) { e6[j] = expf(tv[j] - tv[0]); s6 += e6[j]; }
        float is6 = 1.0f / s6;
        float sba = 0.0f, sbb = 0.0f;
        #pragma unroll
        for (int j = 0; j < 6; j++) {
            float v = e6[j] * is6;
            if (ti[j] == lane)      sba = v;
            if (ti[j] == lane + 32) sbb = v;
        }

        float fla = la ? 1.0f : 0.0f, flb = lb ? 1.0f : 0.0f;
        float ma = wa * ka * fla + 0.18f * sba;
        float mb = wb * kb * flb + 0.18f * sbb;
        float smx = ma + mb;
        #pragma unroll
        for (int o = 16; o; o >>= 1) smx += __shfl_xor_sync(F, smx, o);
        float invd = 1.0f / fmaxf(smx, 1e-6f);
        float Wa = ma * invd, Wb = mb * invd;

        out_w[(size_t)tg * PP + lane]      = Wa;
        out_w[(size_t)tg * PP + 32 + lane] = Wb;

        float lm = Wa * fla + Wb * flb;
        float bm = Wa * (1.0f - fla) + Wb * (1.0f - flb);
        float md = Wa * da + Wb * db;
        #pragma unroll
        for (int o = 16; o; o >>= 1) {
            lm += __shfl_xor_sync(F, lm, o);
            bm += __shfl_xor_sync(F, bm, o);
            md += __shfl_xor_sync(F, md, o);
        }

        float pacc[6] = {0, 0, 0, 0, 0, 0};
        unsigned bal0 = __ballot_sync(F, Wa != 0.0f);
        unsigned bal1 = __ballot_sync(F, Wb != 0.0f);
        while (bal0) {
            int p = __ffs(bal0) - 1; bal0 &= bal0 - 1;
            float wv = __shfl_sync(F, Wa, p);
            const float* row = patch_values + p * H;
            #pragma unroll
            for (int j = 0; j < 6; j++) pacc[j] += wv * __ldg(row + lane + 32 * j);
        }
        while (bal1) {
            int p = __ffs(bal1) - 1; bal1 &= bal1 - 1;
            float wv = __shfl_sync(F, Wb, p);
            const float* row = patch_values + (p + 32) * H;
            #pragma unroll
            for (int j = 0; j < 6; j++) pacc[j] += wv * __ldg(row + lane + 32 * j);
        }
        #pragma unroll
        for (int j = 0; j < 6; j++) out_ps[(size_t)tg * H + lane + 32 * j] = pacc[j];

        if (lane == 0) {
            out_anchor[(size_t)tg * 3 + 0] = ax;
            out_anchor[(size_t)tg * 3 + 1] = ay;
            out_anchor[(size_t)tg * 3 + 2] = az;
            out_lm[tg]  = lm;
            out_bm[tg]  = bm;
            out_md[tg]  = md;
            out_rad[tg] = RAD;
            out_bs[tg]  = 0.18f;
        }
    }
}

// ---- pass 2: recompute flagged tokens with EXACT R2 fp32 math ----
__global__ __launch_bounds__(256)
void fixup(const float* __restrict__ token_state,
           const float* __restrict__ prev_state,
           const float* __restrict__ W_sel,
           const float* __restrict__ b_sel,
           const float* __restrict__ W_br,
           const float* __restrict__ b_br,
           const float* __restrict__ patch_values,
           const float* __restrict__ patch_positions,
           float* __restrict__ out_ps,
           float* __restrict__ out_w,
           float* __restrict__ out_anchor,
           float* __restrict__ out_lm,
           float* __restrict__ out_bm,
           float* __restrict__ out_md,
           float* __restrict__ out_rad,
           float* __restrict__ out_bs)
{
    const unsigned F = 0xffffffffu;
    const int lane  = threadIdx.x & 31;
    const int warpG = (blockIdx.x * blockDim.x + threadIdx.x) >> 5;
    const int nwarp = (gridDim.x * blockDim.x) >> 5;
    const int n = g_cnt;

    const float PXa = __ldg(&patch_positions[lane * 3 + 0]);
    const float PYa = __ldg(&patch_positions[lane * 3 + 1]);
    const float PZa = __ldg(&patch_positions[lane * 3 + 2]);
    const float PXb = __ldg(&patch_positions[(lane + 32) * 3 + 0]);
    const float PYb = __ldg(&patch_positions[(lane + 32) * 3 + 1]);
    const float PZb = __ldg(&patch_positions[(lane + 32) * 3 + 2]);
    const float RAD  = 0.42f;
    const float NEGK = -1.0f / (2.0f * 0.42f * 0.42f);

    for (int i = warpG; i < n; i += nwarp) {
        const int tg = g_list[i];
        const float* q1 = token_state + (size_t)tg * H;
        const float* q2 = prev_state + (size_t)tg * H;
        const float* w0 = W_sel + (size_t)lane * 384;
        const float* w1 = W_sel + (size_t)(lane + 32) * 384;
        const float* w2 = W_br + (size_t)lane * 384;
        const float* w3 = W_br + (size_t)(lane + 32) * 384;

        float a0 = 0.f, a1 = 0.f, a2 = 0.f, a3 = 0.f;
        #pragma unroll 8
        for (int k = 0; k < 192; k++) {
            float q = __ldg(q1 + k);
            a0 = fmaf(q, __ldg(w0 + k), a0);
            a1 = fmaf(q, __ldg(w1 + k), a1);
            a2 = fmaf(q, __ldg(w2 + k), a2);
            a3 = fmaf(q, __ldg(w3 + k), a3);
        }
        #pragma unroll 8
        for (int k = 0; k < 192; k++) {
            float q = __ldg(q2 + k);
            a0 = fmaf(q, __ldg(w0 + 192 + k), a0);
            a1 = fmaf(q, __ldg(w1 + 192 + k), a1);
            a2 = fmaf(q, __ldg(w2 + 192 + k), a2);
            a3 = fmaf(q, __ldg(w3 + 192 + k), a3);
        }
        float ba = a0 + __ldg(b_sel + lane);
        float bb = a1 + __ldg(b_sel + lane + 32);
        float ga = a2 + __ldg(b_br + lane);
        float gb = a3 + __ldg(b_br + lane + 32);

        float mx = fmaxf(ba, bb);
        #pragma unroll
        for (int o = 16; o; o >>= 1) mx = fmaxf(mx, __shfl_xor_sync(F, mx, o));
        float ea = expf(ba - mx), eb = expf(bb - mx);
        float s = ea + eb;
        #pragma unroll
        for (int o = 16; o; o >>= 1) s += __shfl_xor_sync(F, s, o);
        float inv = 1.0f / s;
        float wa = ea * inv, wb = eb * inv;

        float ax = wa * PXa + wb * PXb;
        float ay = wa * PYa + wb * PYb;
        float az = wa * PZa + wb * PZb;
        #pragma unroll
        for (int o = 16; o; o >>= 1) {
            ax += __shfl_xor_sync(F, ax, o);
            ay += __shfl_xor_sync(F, ay, o);
            az += __shfl_xor_sync(F, az, o);
        }

        float dxa = ax - PXa, dya = ay - PYa, dza = az - PZa;
        float dxb = ax - PXb, dyb = ay - PYb, dzb = az - PZb;
        float da = sqrtf(dxa * dxa + dya * dya + dza * dza);
        float db = sqrtf(dxb * dxb + dyb * dyb + dzb * dzb);
        float ka = expf(da * da * NEGK);
        float kb = expf(db * db * NEGK);
        bool la = (da <= RAD), lb = (db <= RAD);

        unsigned long long keya = (((unsigned long long)__float_as_uint(da)) << 32) | (unsigned)lane;
        unsigned long long keyb = (((unsigned long long)__float_as_uint(db)) << 32) | (unsigned)(lane + 32);
        unsigned long long kmin = keya < keyb ? keya : keyb;
        #pragma unroll
        for (int o = 16; o; o >>= 1) {
            unsigned long long ok = __shfl_xor_sync(F, kmin, o);
            if (ok < kmin) kmin = ok;
        }
        int nearest = (int)(kmin & 0x3fu);
        la = la || (lane == nearest);
        lb = lb || (lane + 32 == nearest);

        float va_ = la ? -1e9f : ga;
        float vb_ = lb ? -1e9f : gb;
        float tv[6]; int ti[6];
        #pragma unroll
        for (int j = 0; j < 6; j++) {
            float bv; int bi;
            if (va_ >= vb_) { bv = va_; bi = lane; } else { bv = vb_; bi = lane + 32; }
            #pragma unroll
            for (int o = 16; o; o >>= 1) {
                float ov = __shfl_xor_sync(F, bv, o);
                int   oi = __shfl_xor_sync(F, bi, o);
                if (ov > bv || (ov == bv && oi < bi)) { bv = ov; bi = oi; }
            }
            tv[j] = bv; ti[j] = bi;
            if (bi == lane)      va_ = -3.4e38f;
            if (bi == lane + 32) vb_ = -3.4e38f;
        }
        float s6 = 0.0f, e6[6];
        #pragma unroll
        for (int j = 0; j < 6; j++) { e6[j] = expf(tv[j] - tv[0]); s6 += e6[j]; }
        float is6 = 1.0f / s6;
        float sba = 0.0f, sbb = 0.0f;
        #pragma unroll
        for (int j = 0; j < 6; j++) {
            float v = e6[j] * is6;
            if (ti[j] == lane)      sba = v;
            if (ti[j] == lane + 32) sbb = v;
        }

        float fla = la ? 1.0f : 0.0f, flb = lb ? 1.0f : 0.0f;
        float ma = wa * ka * fla + 0.18f * sba;
        float mb = wb * kb * flb + 0.18f * sbb;
        float smx = ma + mb;
        #pragma unroll
        for (int o = 16; o; o >>= 1) smx += __shfl_xor_sync(F, smx, o);
        float invd = 1.0f / fmaxf(smx, 1e-6f);
        float Wa = ma * invd, Wb = mb * invd;

        out_w[(size_t)tg * PP + lane]      = Wa;
        out_w[(size_t)tg * PP + 32 + lane] = Wb;

        float lm = Wa * fla + Wb * flb;
        float bm = Wa * (1.0f - fla) + Wb * (1.0f - flb);
        float md = Wa * da + Wb * db;
        #pragma unroll
        for (int o = 16; o; o >>= 1) {
            lm += __shfl_xor_sync(F, lm, o);
            bm += __shfl_xor_sync(F, bm, o);
            md += __shfl_xor_sync(F, md, o);
        }

        float pacc[6] = {0, 0, 0, 0, 0, 0};
        unsigned bal0 = __ballot_sync(F, Wa != 0.0f);
        unsigned bal1 = __ballot_sync(F, Wb != 0.0f);
        while (bal0) {
            int p = __ffs(bal0) - 1; bal0 &= bal0 - 1;
            float wv = __shfl_sync(F, Wa, p);
            const float* row = patch_values + p * H;
            #pragma unroll
            for (int j = 0; j < 6; j++) pacc[j] += wv * __ldg(row + lane + 32 * j);
        }
        while (bal1) {
            int p = __ffs(bal1) - 1; bal1 &= bal1 - 1;
            float wv = __shfl_sync(F, Wb, p);
            const float* row = patch_values + (p + 32) * H;
            #pragma unroll
            for (int j = 0; j < 6; j++) pacc[j] += wv * __ldg(row + lane + 32 * j);
        }
        #pragma unroll
        for (int j = 0; j < 6; j++) out_ps[(size_t)tg * H + lane + 32 * j] = pacc[j];

        if (lane == 0) {
            out_anchor[(size_t)tg * 3 + 0] = ax;
            out_anchor[(size_t)tg * 3 + 1] = ay;
            out_anchor[(size_t)tg * 3 + 2] = az;
            out_lm[tg]  = lm;
            out_bm[tg]  = bm;
            out_md[tg]  = md;
            out_rad[tg] = RAD;
            out_bs[tg]  = 0.18f;
        }
    }
}

extern "C" void kernel_launch(void* const* d_in, const int* in_sizes, int n_in,
                              void* d_out, int out_size)
{
    const float* token_state     = (const float*)d_in[0];
    const float* prev_state      = (const float*)d_in[1];
    const float* W_sel           = (const float*)d_in[2];
    const float* b_sel           = (const float*)d_in[3];
    const float* W_br            = (const float*)d_in[4];
    const float* b_br            = (const float*)d_in[5];
    const float* patch_values    = (const float*)d_in[6];
    const float* patch_positions = (const float*)d_in[7];

    const int B = in_sizes[0] / H;
    float* o = (float*)d_out;
    float* out_ps     = o;
    float* out_w      = o + (size_t)B * H;
    float* out_anchor = o + (size_t)B * (H + PP);
    float* out_lm     = o + (size_t)B * (H + PP + 3);
    float* out_bm     = out_lm + B;
    float* out_md     = out_bm + B;
    float* out_rad    = out_md + B;
    float* out_bs     = out_rad + B;

    reset_cnt<<<1, 32>>>();
    prep_w<<<96, 256>>>(W_sel, W_br);

    const int smem_bytes = SMEM_FLOATS * sizeof(float); // 68864
    cudaFuncSetAttribute(taps_mma, cudaFuncAttributeMaxDynamicSharedMemorySize, smem_bytes);

    int grid = (B + 127) / 128;
    taps_mma<<<grid, 256, smem_bytes>>>(
        token_state, prev_state, b_sel, b_br,
        patch_values, patch_positions,
        out_ps, out_w, out_anchor, out_lm, out_bm, out_md, out_rad, out_bs, B);

    fixup<<<256, 256>>>(token_state, prev_state, W_sel, b_sel, W_br, b_br,
                        patch_values, patch_positions,
                        out_ps, out_w, out_anchor, out_lm, out_bm, out_md,
                        out_rad, out_bs);
}

// round 13
// speedup vs baseline: 2.7011x; 1.4057x over previous
#include <cuda_runtime.h>
#include <cuda_bf16.h>
#include <cstdint>

#define H    192
#define PP   64
#define LDT  132
#define TSTR 24
#define TILE_F (128 * TSTR)           // 3072 floats per A buffer

#define SA_BYTES   (2 * TILE_F * 4)   // 24576 B : A f32 double buffer
#define OFF_WB     SA_BYTES           // W packed region (bytes)
#define W_CHUNK_B  8192               // 128 rows * 2 splits * 4 pairs * 8 B
#define OFF_BIAS   (128 * LDT)        // float idx 16896 (Lg aliases tiles)
#define OFF_POS    (OFF_BIAS + 128)
#define SMEM_FLOATS (OFF_POS + 192)   // 17216 floats = 68864 B

#define MARGIN_TH  1e-4f

// pre-split W: [chunk 24][n 128][split 2][pair4][2 u32]
__device__ __align__(16) unsigned int g_wpk[49152];
// transposed fp32 W for fixup: g_wt[k][n], n: 0..63 = W_sel, 64..127 = W_br
__device__ __align__(16) float g_wt[49152];
__device__ int g_cnt;
__device__ int g_list[262144];

__global__ void reset_cnt() { if (threadIdx.x == 0) g_cnt = 0; }

static __device__ __forceinline__ float bf16v(float x) {
    return __bfloat162float(__float2bfloat16(x));
}
static __device__ unsigned int split_bits(float x, int s) {
    float h = bf16v(x);
    if (s == 0) return __float_as_uint(h) >> 16;
    float l = bf16v(x - h);
    return __float_as_uint(l) >> 16;
}

__global__ void prep_w(const float* __restrict__ Ws, const float* __restrict__ Wb) {
    int idx = blockIdx.x * blockDim.x + threadIdx.x;
    // part 1: packed bf16 splits for the MMA kernel (24576 work items)
    if (idx < 24576) {
        int t  = idx & 3;
        int r3 = idx >> 2;
        int s  = r3 & 1;
        int nc = r3 >> 1;
        int n  = nc & 127;
        int c  = nc >> 7;
        const float* row = (n < 64) ? (Ws + (size_t)n * 384) : (Wb + (size_t)(n - 64) * 384);
        int k0 = c * 16 + 2 * t;
        unsigned int p0 = (split_bits(row[k0 + 1], s) << 16) | split_bits(row[k0], s);
        unsigned int p1 = (split_bits(row[k0 + 9], s) << 16) | split_bits(row[k0 + 8], s);
        g_wpk[idx * 2]     = p0;
        g_wpk[idx * 2 + 1] = p1;
    }
    // part 2: fp32 transpose for fixup (49152 elements)
    int j = idx - 24576;
    if (j >= 0 && j < 49152) {
        int n = j & 127;
        int k = j >> 7;
        g_wt[k * 128 + n] = (n < 64) ? Ws[(size_t)n * 384 + k]
                                     : Wb[(size_t)(n - 64) * 384 + k];
    }
}

static __device__ __forceinline__ uint32_t s2u(const void* p) {
    uint32_t a;
    asm("{ .reg .u64 t; cvta.to.shared.u64 t, %1; cvt.u32.u64 %0, t; }" : "=r"(a) : "l"(p));
    return a;
}
static __device__ __forceinline__ void cpasync16(uint32_t s, const void* g) {
    asm volatile("cp.async.cg.shared.global [%0], [%1], 16;" :: "r"(s), "l"(g));
}
static __device__ __forceinline__ void split2b(float x, float y, uint32_t& h, uint32_t& l) {
    asm("cvt.rn.bf16x2.f32 %0, %1, %2;" : "=r"(h) : "f"(y), "f"(x));
    float hx = __uint_as_float(h << 16);
    float hy = __uint_as_float(h & 0xFFFF0000u);
    float lx = x - hx, ly = y - hy;
    asm("cvt.rn.bf16x2.f32 %0, %1, %2;" : "=r"(l) : "f"(ly), "f"(lx));
}
static __device__ __forceinline__ void mma16816(float* d, const uint32_t* a, uint2 b) {
    asm volatile("mma.sync.aligned.m16n8k16.row.col.f32.bf16.bf16.f32 "
        "{%0,%1,%2,%3}, {%4,%5,%6,%7}, {%8,%9}, {%0,%1,%2,%3};"
        : "+f"(d[0]), "+f"(d[1]), "+f"(d[2]), "+f"(d[3])
        : "r"(a[0]), "r"(a[1]), "r"(a[2]), "r"(a[3]), "r"(b.x), "r"(b.y));
}

__global__ __launch_bounds__(256, 2)
void taps_mma(const float* __restrict__ token_state,
              const float* __restrict__ prev_state,
              const float* __restrict__ b_sel,
              const float* __restrict__ b_br,
              const float* __restrict__ patch_values,
              const float* __restrict__ patch_positions,
              float* __restrict__ out_ps,
              float* __restrict__ out_w,
              float* __restrict__ out_anchor,
              float* __restrict__ out_lm,
              float* __restrict__ out_bm,
              float* __restrict__ out_md,
              float* __restrict__ out_rad,
              float* __restrict__ out_bs,
              int B)
{
    extern __shared__ float smem[];
    float* sA   = smem;
    char*  smwc = (char*)smem + OFF_WB;
    float* Lg   = smem;
    float* bias = smem + OFF_BIAS;
    float* posx = smem + OFF_POS;
    float* posy = posx + 64;
    float* posz = posy + 64;

    const int tid  = threadIdx.x;
    const int wid  = tid >> 5;
    const int lane = tid & 31;
    const int m0   = blockIdx.x * 128;

    if (tid < 64) {
        bias[tid]      = b_sel[tid];
        bias[64 + tid] = b_br[tid];
        posx[tid] = patch_positions[tid * 3 + 0];
        posy[tid] = patch_positions[tid * 3 + 1];
        posz[tid] = patch_positions[tid * 3 + 2];
    }

    const uint32_t sAb = s2u(sA);
    const uint32_t sWb = s2u(smwc);
    const char* wsrc = (const char*)g_wpk;

    const int wm   = wid & 3;
    const int wn   = wid >> 2;
    const int roff = wm * 32;
    const int noff = wn * 64;
    const int g    = lane >> 2;
    const int t2   = lane & 3;

    float acc[2][8][4];
    #pragma unroll
    for (int mi = 0; mi < 2; mi++)
        #pragma unroll
        for (int j = 0; j < 8; j++)
            #pragma unroll
            for (int q = 0; q < 4; q++) acc[mi][j][q] = 0.0f;

    const int r_a = tid >> 2,         s_a = tid & 3;
    const int r_b = (tid + 256) >> 2, s_b = tid & 3;

    auto load_chunk = [&](int c, int buf) {
        const float* qs = (c < 12) ? token_state : prev_state;
        const int q0 = (c % 12) * 16;
        cpasync16(sAb + (uint32_t)(buf * TILE_F + r_a * TSTR + s_a * 4) * 4,
                  qs + (size_t)(m0 + r_a) * H + q0 + s_a * 4);
        cpasync16(sAb + (uint32_t)(buf * TILE_F + r_b * TSTR + s_b * 4) * 4,
                  qs + (size_t)(m0 + r_b) * H + q0 + s_b * 4);
        #pragma unroll
        for (int q = 0; q < 2; q++)
            cpasync16(sWb + buf * W_CHUNK_B + tid * 16 + q * 4096,
                      wsrc + (size_t)c * W_CHUNK_B + tid * 16 + q * 4096);
        asm volatile("cp.async.commit_group;");
    };

    load_chunk(0, 0);

    for (int c = 0; c < 24; c++) {
        const int buf = c & 1;
        if (c < 23) {
            load_chunk(c + 1, buf ^ 1);
            asm volatile("cp.async.wait_group 1;");
        } else {
            asm volatile("cp.async.wait_group 0;");
        }
        __syncthreads();

        uint32_t Ah[2][4], Al[2][4];
        #pragma unroll
        for (int mi = 0; mi < 2; mi++) {
            const float* a0p = sA + buf * TILE_F + (roff + mi * 16 + g) * TSTR + 2 * t2;
            const float* a1p = a0p + 8 * TSTR;
            float2 q00 = *(const float2*)a0p;
            float2 q10 = *(const float2*)a1p;
            float2 q01 = *(const float2*)(a0p + 8);
            float2 q11 = *(const float2*)(a1p + 8);
            split2b(q00.x, q00.y, Ah[mi][0], Al[mi][0]);
            split2b(q10.x, q10.y, Ah[mi][1], Al[mi][1]);
            split2b(q01.x, q01.y, Ah[mi][2], Al[mi][2]);
            split2b(q11.x, q11.y, Ah[mi][3], Al[mi][3]);
        }

        const char* wb = smwc + buf * W_CHUNK_B;
        #pragma unroll
        for (int j = 0; j < 8; j++) {
            const int n = noff + j * 8 + g;
            uint2 bh = *(const uint2*)(wb + ((n * 2 + 0) * 4 + t2) * 8);
            uint2 bl = *(const uint2*)(wb + ((n * 2 + 1) * 4 + t2) * 8);
            #pragma unroll
            for (int mi = 0; mi < 2; mi++) {
                mma16816(acc[mi][j], Ah[mi], bh);
                mma16816(acc[mi][j], Ah[mi], bl);
                mma16816(acc[mi][j], Al[mi], bh);
            }
        }
        __syncthreads();
    }

    #pragma unroll
    for (int mi = 0; mi < 2; mi++) {
        const int r0 = roff + mi * 16 + g;
        #pragma unroll
        for (int j = 0; j < 8; j++) {
            const int cb = noff + j * 8 + 2 * t2;
            float2 v0 = {acc[mi][j][0] + bias[cb], acc[mi][j][1] + bias[cb + 1]};
            float2 v1 = {acc[mi][j][2] + bias[cb], acc[mi][j][3] + bias[cb + 1]};
            *(float2*)&Lg[r0 * LDT + cb]       = v0;
            *(float2*)&Lg[(r0 + 8) * LDT + cb] = v1;
        }
    }
    __syncthreads();

    // ---- postprocess + margin flagging ----
    const unsigned F = 0xffffffffu;
    const float PXa = posx[lane],      PYa = posy[lane],      PZa = posz[lane];
    const float PXb = posx[lane + 32], PYb = posy[lane + 32], PZb = posz[lane + 32];
    const float RAD  = 0.42f;
    const float NEGK = -1.0f / (2.0f * 0.42f * 0.42f);

    for (int r = 0; r < 16; r++) {
        int t  = wid * 16 + r;
        int tg = m0 + t;
        if (tg >= B) break;
        const float* L = &Lg[t * LDT];
        float ba = L[lane],      bb = L[lane + 32];
        float ga = L[lane + 64], gb = L[lane + 96];

        float mx = fmaxf(ba, bb);
        #pragma unroll
        for (int o = 16; o; o >>= 1) mx = fmaxf(mx, __shfl_xor_sync(F, mx, o));
        float ea = expf(ba - mx), eb = expf(bb - mx);
        float s = ea + eb;
        #pragma unroll
        for (int o = 16; o; o >>= 1) s += __shfl_xor_sync(F, s, o);
        float inv = 1.0f / s;
        float wa = ea * inv, wb = eb * inv;

        float ax = wa * PXa + wb * PXb;
        float ay = wa * PYa + wb * PYb;
        float az = wa * PZa + wb * PZb;
        #pragma unroll
        for (int o = 16; o; o >>= 1) {
            ax += __shfl_xor_sync(F, ax, o);
            ay += __shfl_xor_sync(F, ay, o);
            az += __shfl_xor_sync(F, az, o);
        }

        float dxa = ax - PXa, dya = ay - PYa, dza = az - PZa;
        float dxb = ax - PXb, dyb = ay - PYb, dzb = az - PZb;
        float da = sqrtf(dxa * dxa + dya * dya + dza * dza);
        float db = sqrtf(dxb * dxb + dyb * dyb + dzb * dzb);
        float ka = expf(da * da * NEGK);
        float kb = expf(db * db * NEGK);
        bool la = (da <= RAD), lb = (db <= RAD);

        unsigned long long keya = (((unsigned long long)__float_as_uint(da)) << 32) | (unsigned)lane;
        unsigned long long keyb = (((unsigned long long)__float_as_uint(db)) << 32) | (unsigned)(lane + 32);
        unsigned long long kmin = keya < keyb ? keya : keyb;
        #pragma unroll
        for (int o = 16; o; o >>= 1) {
            unsigned long long ok = __shfl_xor_sync(F, kmin, o);
            if (ok < kmin) kmin = ok;
        }
        int nearest = (int)(kmin & 0x3fu);
        float dmin = __uint_as_float((unsigned)(kmin >> 32));
        la = la || (lane == nearest);
        lb = lb || (lane + 32 == nearest);

        float va_ = la ? -1e9f : ga;
        float vb_ = lb ? -1e9f : gb;
        float tv[6]; int ti[6];
        #pragma unroll
        for (int j = 0; j < 6; j++) {
            float bv; int bi;
            if (va_ >= vb_) { bv = va_; bi = lane; } else { bv = vb_; bi = lane + 32; }
            #pragma unroll
            for (int o = 16; o; o >>= 1) {
                float ov = __shfl_xor_sync(F, bv, o);
                int   oi = __shfl_xor_sync(F, bi, o);
                if (ov > bv || (ov == bv && oi < bi)) { bv = ov; bi = oi; }
            }
            tv[j] = bv; ti[j] = bi;
            if (bi == lane)      va_ = -3.4e38f;
            if (bi == lane + 32) vb_ = -3.4e38f;
        }
        float v7 = fmaxf(va_, vb_);
        float mr = fminf(fabsf(da - RAD), fabsf(db - RAD));
        float c1 = (lane == nearest)      ? 3.4e38f : da;
        float c2 = (lane + 32 == nearest) ? 3.4e38f : db;
        float d2 = fminf(c1, c2);
        #pragma unroll
        for (int o = 16; o; o >>= 1) {
            v7 = fmaxf(v7, __shfl_xor_sync(F, v7, o));
            mr = fminf(mr, __shfl_xor_sync(F, mr, o));
            d2 = fminf(d2, __shfl_xor_sync(F, d2, o));
        }
        if (lane == 0) {
            float mm = fminf(tv[5] - v7, fminf(mr, d2 - dmin));
            if (mm < MARGIN_TH) {
                int slot = atomicAdd(&g_cnt, 1);
                g_list[slot] = tg;
            }
        }

        float s6 = 0.0f, e6[6];
        #pragma unroll
        for (int j = 0; j < 6; j++) { e6[j] = expf(tv[j] - tv[0]); s6 += e6[j]; }
        float is6 = 1.0f / s6;
        float sba = 0.0f, sbb = 0.0f;
        #pragma unroll
        for (int j = 0; j < 6; j++) {
            float v = e6[j] * is6;
            if (ti[j] == lane)      sba = v;
            if (ti[j] == lane + 32) sbb = v;
        }

        float fla = la ? 1.0f : 0.0f, flb = lb ? 1.0f : 0.0f;
        float ma = wa * ka * fla + 0.18f * sba;
        float mb = wb * kb * flb + 0.18f * sbb;
        float smx = ma + mb;
        #pragma unroll
        for (int o = 16; o; o >>= 1) smx += __shfl_xor_sync(F, smx, o);
        float invd = 1.0f / fmaxf(smx, 1e-6f);
        float Wa = ma * invd, Wb = mb * invd;

        out_w[(size_t)tg * PP + lane]      = Wa;
        out_w[(size_t)tg * PP + 32 + lane] = Wb;

        float lm = Wa * fla + Wb * flb;
        float bm = Wa * (1.0f - fla) + Wb * (1.0f - flb);
        float md = Wa * da + Wb * db;
        #pragma unroll
        for (int o = 16; o; o >>= 1) {
            lm += __shfl_xor_sync(F, lm, o);
            bm += __shfl_xor_sync(F, bm, o);
            md += __shfl_xor_sync(F, md, o);
        }

        float pacc[6] = {0, 0, 0, 0, 0, 0};
        unsigned bal0 = __ballot_sync(F, Wa != 0.0f);
        unsigned bal1 = __ballot_sync(F, Wb != 0.0f);
        while (bal0) {
            int p = __ffs(bal0) - 1; bal0 &= bal0 - 1;
            float wv = __shfl_sync(F, Wa, p);
            const float* row = patch_values + p * H;
            #pragma unroll
            for (int j = 0; j < 6; j++) pacc[j] += wv * __ldg(row + lane + 32 * j);
        }
        while (bal1) {
            int p = __ffs(bal1) - 1; bal1 &= bal1 - 1;
            float wv = __shfl_sync(F, Wb, p);
            const float* row = patch_values + (p + 32) * H;
            #pragma unroll
            for (int j = 0; j < 6; j++) pacc[j] += wv * __ldg(row + lane + 32 * j);
        }
        #pragma unroll
        for (int j = 0; j < 6; j++) out_ps[(size_t)tg * H + lane + 32 * j] = pacc[j];

        if (lane == 0) {
            out_anchor[(size_t)tg * 3 + 0] = ax;
            out_anchor[(size_t)tg * 3 + 1] = ay;
            out_anchor[(size_t)tg * 3 + 2] = az;
            out_lm[tg]  = lm;
            out_bm[tg]  = bm;
            out_md[tg]  = md;
            out_rad[tg] = RAD;
            out_bs[tg]  = 0.18f;
        }
    }
}

// ---- pass 2: recompute flagged tokens; coalesced transposed-W GEMV,
//      EXACT R2 sequential-k fmaf chain per output ----
__global__ __launch_bounds__(256)
void fixup(const float* __restrict__ token_state,
           const float* __restrict__ prev_state,
           const float* __restrict__ b_sel,
           const float* __restrict__ b_br,
           const float* __restrict__ patch_values,
           const float* __restrict__ patch_positions,
           float* __restrict__ out_ps,
           float* __restrict__ out_w,
           float* __restrict__ out_anchor,
           float* __restrict__ out_lm,
           float* __restrict__ out_bm,
           float* __restrict__ out_md,
           float* __restrict__ out_rad,
           float* __restrict__ out_bs)
{
    const unsigned F = 0xffffffffu;
    const int lane  = threadIdx.x & 31;
    const int warpG = (blockIdx.x * blockDim.x + threadIdx.x) >> 5;
    const int nwarp = (gridDim.x * blockDim.x) >> 5;
    const int n = g_cnt;

    const float PXa = __ldg(&patch_positions[lane * 3 + 0]);
    const float PYa = __ldg(&patch_positions[lane * 3 + 1]);
    const float PZa = __ldg(&patch_positions[lane * 3 + 2]);
    const float PXb = __ldg(&patch_positions[(lane + 32) * 3 + 0]);
    const float PYb = __ldg(&patch_positions[(lane + 32) * 3 + 1]);
    const float PZb = __ldg(&patch_positions[(lane + 32) * 3 + 2]);
    const float RAD  = 0.42f;
    const float NEGK = -1.0f / (2.0f * 0.42f * 0.42f);

    for (int i = warpG; i < n; i += nwarp) {
        const int tg = g_list[i];
        const float* q1 = token_state + (size_t)tg * H;
        const float* q2 = prev_state + (size_t)tg * H;

        // coalesced q preload: qv[j] = q[lane + 32j]
        float qv[12];
        #pragma unroll
        for (int j = 0; j < 6; j++) qv[j]     = __ldg(q1 + lane + 32 * j);
        #pragma unroll
        for (int j = 0; j < 6; j++) qv[6 + j] = __ldg(q2 + lane + 32 * j);

        // exact R2 order: sequential k ascending, 4 independent fmaf chains.
        // W via transposed g_wt: lane-consecutive -> fully coalesced.
        float a0 = 0.f, a1 = 0.f, a2 = 0.f, a3 = 0.f;
        #pragma unroll
        for (int j = 0; j < 12; j++) {
            #pragma unroll 8
            for (int kk = 0; kk < 32; kk++) {
                float q = __shfl_sync(F, qv[j], kk);
                const float* wr = g_wt + (j * 32 + kk) * 128;
                a0 = fmaf(q, __ldg(wr + lane),      a0);
                a1 = fmaf(q, __ldg(wr + lane + 32), a1);
                a2 = fmaf(q, __ldg(wr + lane + 64), a2);
                a3 = fmaf(q, __ldg(wr + lane + 96), a3);
            }
        }
        float ba = a0 + __ldg(b_sel + lane);
        float bb = a1 + __ldg(b_sel + lane + 32);
        float ga = a2 + __ldg(b_br + lane);
        float gb = a3 + __ldg(b_br + lane + 32);

        float mx = fmaxf(ba, bb);
        #pragma unroll
        for (int o = 16; o; o >>= 1) mx = fmaxf(mx, __shfl_xor_sync(F, mx, o));
        float ea = expf(ba - mx), eb = expf(bb - mx);
        float s = ea + eb;
        #pragma unroll
        for (int o = 16; o; o >>= 1) s += __shfl_xor_sync(F, s, o);
        float inv = 1.0f / s;
        float wa = ea * inv, wb = eb * inv;

        float ax = wa * PXa + wb * PXb;
        float ay = wa * PYa + wb * PYb;
        float az = wa * PZa + wb * PZb;
        #pragma unroll
        for (int o = 16; o; o >>= 1) {
            ax += __shfl_xor_sync(F, ax, o);
            ay += __shfl_xor_sync(F, ay, o);
            az += __shfl_xor_sync(F, az, o);
        }

        float dxa = ax - PXa, dya = ay - PYa, dza = az - PZa;
        float dxb = ax - PXb, dyb = ay - PYb, dzb = az - PZb;
        float da = sqrtf(dxa * dxa + dya * dya + dza * dza);
        float db = sqrtf(dxb * dxb + dyb * dyb + dzb * dzb);
        float ka = expf(da * da * NEGK);
        float kb = expf(db * db * NEGK);
        bool la = (da <= RAD), lb = (db <= RAD);

        unsigned long long keya = (((unsigned long long)__float_as_uint(da)) << 32) | (unsigned)lane;
        unsigned long long keyb = (((unsigned long long)__float_as_uint(db)) << 32) | (unsigned)(lane + 32);
        unsigned long long kmin = keya < keyb ? keya : keyb;
        #pragma unroll
        for (int o = 16; o; o >>= 1) {
            unsigned long long ok = __shfl_xor_sync(F, kmin, o);
            if (ok < kmin) kmin = ok;
        }
        int nearest = (int)(kmin & 0x3fu);
        la = la || (lane == nearest);
        lb = lb || (lane + 32 == nearest);

        float va_ = la ? -1e9f : ga;
        float vb_ = lb ? -1e9f : gb;
        float tv[6]; int ti[6];
        #pragma unroll
        for (int j = 0; j < 6; j++) {
            float bv; int bi;
            if (va_ >= vb_) { bv = va_; bi = lane; } else { bv = vb_; bi = lane + 32; }
            #pragma unroll
            for (int o = 16; o; o >>= 1) {
                float ov = __shfl_xor_sync(F, bv, o);
                int   oi = __shfl_xor_sync(F, bi, o);
                if (ov > bv || (ov == bv && oi < bi)) { bv = ov; bi = oi; }
            }
            tv[j] = bv; ti[j] = bi;
            if (bi == lane)      va_ = -3.4e38f;
            if (bi == lane + 32) vb_ = -3.4e38f;
        }
        float s6 = 0.0f, e6[6];
        #pragma unroll
        for (int j = 0; j < 6; j++) { e6[j] = expf(tv[j] - tv[0]); s6 += e6[j]; }
        float is6 = 1.0f / s6;
        float sba = 0.0f, sbb = 0.0f;
        #pragma unroll
        for (int j = 0; j < 6; j++) {
            float v = e6[j] * is6;
            if (ti[j] == lane)      sba = v;
            if (ti[j] == lane + 32) sbb = v;
        }

        float fla = la ? 1.0f : 0.0f, flb = lb ? 1.0f : 0.0f;
        float ma = wa * ka * fla + 0.18f * sba;
        float mb = wb * kb * flb + 0.18f * sbb;
        float smx = ma + mb;
        #pragma unroll
        for (int o = 16; o; o >>= 1) smx += __shfl_xor_sync(F, smx, o);
        float invd = 1.0f / fmaxf(smx, 1e-6f);
        float Wa = ma * invd, Wb = mb * invd;

        out_w[(size_t)tg * PP + lane]      = Wa;
        out_w[(size_t)tg * PP + 32 + lane] = Wb;

        float lm = Wa * fla + Wb * flb;
        float bm = Wa * (1.0f - fla) + Wb * (1.0f - flb);
        float md = Wa * da + Wb * db;
        #pragma unroll
        for (int o = 16; o; o >>= 1) {
            lm += __shfl_xor_sync(F, lm, o);
            bm += __shfl_xor_sync(F, bm, o);
            md += __shfl_xor_sync(F, md, o);
        }

        float pacc[6] = {0, 0, 0, 0, 0, 0};
        unsigned bal0 = __ballot_sync(F, Wa != 0.0f);
        unsigned bal1 = __ballot_sync(F, Wb != 0.0f);
        while (bal0) {
            int p = __ffs(bal0) - 1; bal0 &= bal0 - 1;
            float wv = __shfl_sync(F, Wa, p);
            const float* row = patch_values + p * H;
            #pragma unroll
            for (int j = 0; j < 6; j++) pacc[j] += wv * __ldg(row + lane + 32 * j);
        }
        while (bal1) {
            int p = __ffs(bal1) - 1; bal1 &= bal1 - 1;
            float wv = __shfl_sync(F, Wb, p);
            const float* row = patch_values + (p + 32) * H;
            #pragma unroll
            for (int j = 0; j < 6; j++) pacc[j] += wv * __ldg(row + lane + 32 * j);
        }
        #pragma unroll
        for (int j = 0; j < 6; j++) out_ps[(size_t)tg * H + lane + 32 * j] = pacc[j];

        if (lane == 0) {
            out_anchor[(size_t)tg * 3 + 0] = ax;
            out_anchor[(size_t)tg * 3 + 1] = ay;
            out_anchor[(size_t)tg * 3 + 2] = az;
            out_lm[tg]  = lm;
            out_bm[tg]  = bm;
            out_md[tg]  = md;
            out_rad[tg] = RAD;
            out_bs[tg]  = 0.18f;
        }
    }
}

extern "C" void kernel_launch(void* const* d_in, const int* in_sizes, int n_in,
                              void* d_out, int out_size)
{
    const float* token_state     = (const float*)d_in[0];
    const float* prev_state      = (const float*)d_in[1];
    const float* W_sel           = (const float*)d_in[2];
    const float* b_sel           = (const float*)d_in[3];
    const float* W_br            = (const float*)d_in[4];
    const float* b_br            = (const float*)d_in[5];
    const float* patch_values    = (const float*)d_in[6];
    const float* patch_positions = (const float*)d_in[7];

    const int B = in_sizes[0] / H;
    float* o = (float*)d_out;
    float* out_ps     = o;
    float* out_w      = o + (size_t)B * H;
    float* out_anchor = o + (size_t)B * (H + PP);
    float* out_lm     = o + (size_t)B * (H + PP + 3);
    float* out_bm     = out_lm + B;
    float* out_md     = out_bm + B;
    float* out_rad    = out_md + B;
    float* out_bs     = out_rad + B;

    reset_cnt<<<1, 32>>>();
    prep_w<<<288, 256>>>(W_sel, W_br);   // 73728 work items

    const int smem_bytes = SMEM_FLOATS * sizeof(float); // 68864
    cudaFuncSetAttribute(taps_mma, cudaFuncAttributeMaxDynamicSharedMemorySize, smem_bytes);

    int grid = (B + 127) / 128;
    taps_mma<<<grid, 256, smem_bytes>>>(
        token_state, prev_state, b_sel, b_br,
        patch_values, patch_positions,
        out_ps, out_w, out_anchor, out_lm, out_bm, out_md, out_rad, out_bs, B);

    fixup<<<256, 256>>>(token_state, prev_state, b_sel, b_br,
                        patch_values, patch_positions,
                        out_ps, out_w, out_anchor, out_lm, out_bm, out_md,
                        out_rad, out_bs);
}

// round 16
// speedup vs baseline: 2.9135x; 1.0786x over previous
#include <cuda_runtime.h>
#include <cuda_bf16.h>
#include <cstdint>

#define H    192
#define PP   64
#define LDT  132
#define TSTR 24
#define TILE_F (128 * TSTR)           // 3072 floats per A buffer

#define SA_BYTES   (2 * TILE_F * 4)   // 24576 B : A f32 double buffer
#define OFF_WB     SA_BYTES           // W packed region (bytes)
#define W_CHUNK_B  8192               // 128 rows * 2 splits * 4 pairs * 8 B
#define OFF_BIAS   (128 * LDT)        // float idx 16896 (Lg aliases tiles)
#define OFF_POS    (OFF_BIAS + 128)
#define SMEM_FLOATS (OFF_POS + 192)   // 17216 floats = 68864 B

#define MARGIN_TH  1e-4f

// pre-split W: [chunk 24][n 128][split 2][pair4][2 u32]
__device__ __align__(16) unsigned int g_wpk[49152];
// transposed fp32 W for fixup: g_wt[k][n], n: 0..63 = W_sel, 64..127 = W_br
__device__ __align__(16) float g_wt[49152];
__device__ int g_cnt;
__device__ int g_list[262144];

__global__ void reset_cnt() { if (threadIdx.x == 0) g_cnt = 0; }

static __device__ __forceinline__ float bf16v(float x) {
    return __bfloat162float(__float2bfloat16(x));
}
static __device__ unsigned int split_bits(float x, int s) {
    float h = bf16v(x);
    if (s == 0) return __float_as_uint(h) >> 16;
    float l = bf16v(x - h);
    return __float_as_uint(l) >> 16;
}

__global__ void prep_w(const float* __restrict__ Ws, const float* __restrict__ Wb) {
    int idx = blockIdx.x * blockDim.x + threadIdx.x;
    if (idx < 24576) {
        int t  = idx & 3;
        int r3 = idx >> 2;
        int s  = r3 & 1;
        int nc = r3 >> 1;
        int n  = nc & 127;
        int c  = nc >> 7;
        const float* row = (n < 64) ? (Ws + (size_t)n * 384) : (Wb + (size_t)(n - 64) * 384);
        int k0 = c * 16 + 2 * t;
        unsigned int p0 = (split_bits(row[k0 + 1], s) << 16) | split_bits(row[k0], s);
        unsigned int p1 = (split_bits(row[k0 + 9], s) << 16) | split_bits(row[k0 + 8], s);
        g_wpk[idx * 2]     = p0;
        g_wpk[idx * 2 + 1] = p1;
    }
    int j = idx - 24576;
    if (j >= 0 && j < 49152) {
        int n = j & 127;
        int k = j >> 7;
        g_wt[k * 128 + n] = (n < 64) ? Ws[(size_t)n * 384 + k]
                                     : Wb[(size_t)(n - 64) * 384 + k];
    }
}

static __device__ __forceinline__ uint32_t s2u(const void* p) {
    uint32_t a;
    asm("{ .reg .u64 t; cvta.to.shared.u64 t, %1; cvt.u32.u64 %0, t; }" : "=r"(a) : "l"(p));
    return a;
}
static __device__ __forceinline__ void cpasync16(uint32_t s, const void* g) {
    asm volatile("cp.async.cg.shared.global [%0], [%1], 16;" :: "r"(s), "l"(g));
}
static __device__ __forceinline__ void split2b(float x, float y, uint32_t& h, uint32_t& l) {
    asm("cvt.rn.bf16x2.f32 %0, %1, %2;" : "=r"(h) : "f"(y), "f"(x));
    float hx = __uint_as_float(h << 16);
    float hy = __uint_as_float(h & 0xFFFF0000u);
    float lx = x - hx, ly = y - hy;
    asm("cvt.rn.bf16x2.f32 %0, %1, %2;" : "=r"(l) : "f"(ly), "f"(lx));
}
static __device__ __forceinline__ void mma16816(float* d, const uint32_t* a, uint2 b) {
    asm volatile("mma.sync.aligned.m16n8k16.row.col.f32.bf16.bf16.f32 "
        "{%0,%1,%2,%3}, {%4,%5,%6,%7}, {%8,%9}, {%0,%1,%2,%3};"
        : "+f"(d[0]), "+f"(d[1]), "+f"(d[2]), "+f"(d[3])
        : "r"(a[0]), "r"(a[1]), "r"(a[2]), "r"(a[3]), "r"(b.x), "r"(b.y));
}

__global__ __launch_bounds__(256, 2)
void taps_mma(const float* __restrict__ token_state,
              const float* __restrict__ prev_state,
              const float* __restrict__ b_sel,
              const float* __restrict__ b_br,
              const float* __restrict__ patch_values,
              const float* __restrict__ patch_positions,
              float* __restrict__ out_ps,
              float* __restrict__ out_w,
              float* __restrict__ out_anchor,
              float* __restrict__ out_lm,
              float* __restrict__ out_bm,
              float* __restrict__ out_md,
              float* __restrict__ out_rad,
              float* __restrict__ out_bs,
              int B)
{
    extern __shared__ float smem[];
    float* sA   = smem;
    char*  smwc = (char*)smem + OFF_WB;
    float* Lg   = smem;
    float* bias = smem + OFF_BIAS;
    float* posx = smem + OFF_POS;
    float* posy = posx + 64;
    float* posz = posy + 64;

    const int tid  = threadIdx.x;
    const int wid  = tid >> 5;
    const int lane = tid & 31;
    const int m0   = blockIdx.x * 128;

    if (tid < 64) {
        bias[tid]      = b_sel[tid];
        bias[64 + tid] = b_br[tid];
        posx[tid] = patch_positions[tid * 3 + 0];
        posy[tid] = patch_positions[tid * 3 + 1];
        posz[tid] = patch_positions[tid * 3 + 2];
    }

    const uint32_t sAb = s2u(sA);
    const uint32_t sWb = s2u(smwc);
    const char* wsrc = (const char*)g_wpk;

    const int wm   = wid & 3;
    const int wn   = wid >> 2;
    const int roff = wm * 32;
    const int noff = wn * 64;
    const int g    = lane >> 2;
    const int t2   = lane & 3;

    float acc[2][8][4];
    #pragma unroll
    for (int mi = 0; mi < 2; mi++)
        #pragma unroll
        for (int j = 0; j < 8; j++)
            #pragma unroll
            for (int q = 0; q < 4; q++) acc[mi][j][q] = 0.0f;

    const int r_a = tid >> 2,         s_a = tid & 3;
    const int r_b = (tid + 256) >> 2, s_b = tid & 3;

    auto load_chunk = [&](int c, int buf) {
        const float* qs = (c < 12) ? token_state : prev_state;
        const int q0 = (c % 12) * 16;
        cpasync16(sAb + (uint32_t)(buf * TILE_F + r_a * TSTR + s_a * 4) * 4,
                  qs + (size_t)(m0 + r_a) * H + q0 + s_a * 4);
        cpasync16(sAb + (uint32_t)(buf * TILE_F + r_b * TSTR + s_b * 4) * 4,
                  qs + (size_t)(m0 + r_b) * H + q0 + s_b * 4);
        #pragma unroll
        for (int q = 0; q < 2; q++)
            cpasync16(sWb + buf * W_CHUNK_B + tid * 16 + q * 4096,
                      wsrc + (size_t)c * W_CHUNK_B + tid * 16 + q * 4096);
        asm volatile("cp.async.commit_group;");
    };

    load_chunk(0, 0);

    for (int c = 0; c < 24; c++) {
        const int buf = c & 1;
        if (c < 23) {
            load_chunk(c + 1, buf ^ 1);
            asm volatile("cp.async.wait_group 1;");
        } else {
            asm volatile("cp.async.wait_group 0;");
        }
        __syncthreads();

        uint32_t Ah[2][4], Al[2][4];
        #pragma unroll
        for (int mi = 0; mi < 2; mi++) {
            const float* a0p = sA + buf * TILE_F + (roff + mi * 16 + g) * TSTR + 2 * t2;
            const float* a1p = a0p + 8 * TSTR;
            float2 q00 = *(const float2*)a0p;
            float2 q10 = *(const float2*)a1p;
            float2 q01 = *(const float2*)(a0p + 8);
            float2 q11 = *(const float2*)(a1p + 8);
            split2b(q00.x, q00.y, Ah[mi][0], Al[mi][0]);
            split2b(q10.x, q10.y, Ah[mi][1], Al[mi][1]);
            split2b(q01.x, q01.y, Ah[mi][2], Al[mi][2]);
            split2b(q11.x, q11.y, Ah[mi][3], Al[mi][3]);
        }

        const char* wb = smwc + buf * W_CHUNK_B;
        #pragma unroll
        for (int j = 0; j < 8; j++) {
            const int n = noff + j * 8 + g;
            uint2 bh = *(const uint2*)(wb + ((n * 2 + 0) * 4 + t2) * 8);
            uint2 bl = *(const uint2*)(wb + ((n * 2 + 1) * 4 + t2) * 8);
            #pragma unroll
            for (int mi = 0; mi < 2; mi++) {
                mma16816(acc[mi][j], Ah[mi], bh);
                mma16816(acc[mi][j], Ah[mi], bl);
                mma16816(acc[mi][j], Al[mi], bh);
            }
        }
        __syncthreads();
    }

    #pragma unroll
    for (int mi = 0; mi < 2; mi++) {
        const int r0 = roff + mi * 16 + g;
        #pragma unroll
        for (int j = 0; j < 8; j++) {
            const int cb = noff + j * 8 + 2 * t2;
            float2 v0 = {acc[mi][j][0] + bias[cb], acc[mi][j][1] + bias[cb + 1]};
            float2 v1 = {acc[mi][j][2] + bias[cb], acc[mi][j][3] + bias[cb + 1]};
            *(float2*)&Lg[r0 * LDT + cb]       = v0;
            *(float2*)&Lg[(r0 + 8) * LDT + cb] = v1;
        }
    }
    __syncthreads();

    // ---- postprocess + margin flagging ----
    const unsigned F = 0xffffffffu;
    const float PXa = posx[lane],      PYa = posy[lane],      PZa = posz[lane];
    const float PXb = posx[lane + 32], PYb = posy[lane + 32], PZb = posz[lane + 32];
    const float RAD  = 0.42f;
    const float NEGK = -1.0f / (2.0f * 0.42f * 0.42f);

    for (int r = 0; r < 16; r++) {
        int t  = wid * 16 + r;
        int tg = m0 + t;
        if (tg >= B) break;
        const float* L = &Lg[t * LDT];
        float ba = L[lane],      bb = L[lane + 32];
        float ga = L[lane + 64], gb = L[lane + 96];

        float mx = fmaxf(ba, bb);
        #pragma unroll
        for (int o = 16; o; o >>= 1) mx = fmaxf(mx, __shfl_xor_sync(F, mx, o));
        float ea = expf(ba - mx), eb = expf(bb - mx);
        float s = ea + eb;
        #pragma unroll
        for (int o = 16; o; o >>= 1) s += __shfl_xor_sync(F, s, o);
        float inv = 1.0f / s;
        float wa = ea * inv, wb = eb * inv;

        float ax = wa * PXa + wb * PXb;
        float ay = wa * PYa + wb * PYb;
        float az = wa * PZa + wb * PZb;
        #pragma unroll
        for (int o = 16; o; o >>= 1) {
            ax += __shfl_xor_sync(F, ax, o);
            ay += __shfl_xor_sync(F, ay, o);
            az += __shfl_xor_sync(F, az, o);
        }

        float dxa = ax - PXa, dya = ay - PYa, dza = az - PZa;
        float dxb = ax - PXb, dyb = ay - PYb, dzb = az - PZb;
        float da = sqrtf(dxa * dxa + dya * dya + dza * dza);
        float db = sqrtf(dxb * dxb + dyb * dyb + dzb * dzb);
        float ka = expf(da * da * NEGK);
        float kb = expf(db * db * NEGK);
        bool la = (da <= RAD), lb = (db <= RAD);

        unsigned long long keya = (((unsigned long long)__float_as_uint(da)) << 32) | (unsigned)lane;
        unsigned long long keyb = (((unsigned long long)__float_as_uint(db)) << 32) | (unsigned)(lane + 32);
        unsigned long long kmin = keya < keyb ? keya : keyb;
        #pragma unroll
        for (int o = 16; o; o >>= 1) {
            unsigned long long ok = __shfl_xor_sync(F, kmin, o);
            if (ok < kmin) kmin = ok;
        }
        int nearest = (int)(kmin & 0x3fu);
        float dmin = __uint_as_float((unsigned)(kmin >> 32));
        la = la || (lane == nearest);
        lb = lb || (lane + 32 == nearest);

        float va_ = la ? -1e9f : ga;
        float vb_ = lb ? -1e9f : gb;
        float tv[6]; int ti[6];
        #pragma unroll
        for (int j = 0; j < 6; j++) {
            float bv; int bi;
            if (va_ >= vb_) { bv = va_; bi = lane; } else { bv = vb_; bi = lane + 32; }
            #pragma unroll
            for (int o = 16; o; o >>= 1) {
                float ov = __shfl_xor_sync(F, bv, o);
                int   oi = __shfl_xor_sync(F, bi, o);
                if (ov > bv || (ov == bv && oi < bi)) { bv = ov; bi = oi; }
            }
            tv[j] = bv; ti[j] = bi;
            if (bi == lane)      va_ = -3.4e38f;
            if (bi == lane + 32) vb_ = -3.4e38f;
        }
        float v7 = fmaxf(va_, vb_);
        float mr = fminf(fabsf(da - RAD), fabsf(db - RAD));
        float c1 = (lane == nearest)      ? 3.4e38f : da;
        float c2 = (lane + 32 == nearest) ? 3.4e38f : db;
        float d2 = fminf(c1, c2);
        #pragma unroll
        for (int o = 16; o; o >>= 1) {
            v7 = fmaxf(v7, __shfl_xor_sync(F, v7, o));
            mr = fminf(mr, __shfl_xor_sync(F, mr, o));
            d2 = fminf(d2, __shfl_xor_sync(F, d2, o));
        }
        if (lane == 0) {
            float mm = fminf(tv[5] - v7, fminf(mr, d2 - dmin));
            if (mm < MARGIN_TH) {
                int slot = atomicAdd(&g_cnt, 1);
                g_list[slot] = tg;
            }
        }

        float s6 = 0.0f, e6[6];
        #pragma unroll
        for (int j = 0; j < 6; j++) { e6[j] = expf(tv[j] - tv[0]); s6 += e6[j]; }
        float is6 = 1.0f / s6;
        float sba = 0.0f, sbb = 0.0f;
        #pragma unroll
        for (int j = 0; j < 6; j++) {
            float v = e6[j] * is6;
            if (ti[j] == lane)      sba = v;
            if (ti[j] == lane + 32) sbb = v;
        }

        float fla = la ? 1.0f : 0.0f, flb = lb ? 1.0f : 0.0f;
        float ma = wa * ka * fla + 0.18f * sba;
        float mb = wb * kb * flb + 0.18f * sbb;
        float smx = ma + mb;
        #pragma unroll
        for (int o = 16; o; o >>= 1) smx += __shfl_xor_sync(F, smx, o);
        float invd = 1.0f / fmaxf(smx, 1e-6f);
        float Wa = ma * invd, Wb = mb * invd;

        out_w[(size_t)tg * PP + lane]      = Wa;
        out_w[(size_t)tg * PP + 32 + lane] = Wb;

        float lm = Wa * fla + Wb * flb;
        float bm = Wa * (1.0f - fla) + Wb * (1.0f - flb);
        float md = Wa * da + Wb * db;
        #pragma unroll
        for (int o = 16; o; o >>= 1) {
            lm += __shfl_xor_sync(F, lm, o);
            bm += __shfl_xor_sync(F, bm, o);
            md += __shfl_xor_sync(F, md, o);
        }

        float pacc[6] = {0, 0, 0, 0, 0, 0};
        unsigned bal0 = __ballot_sync(F, Wa != 0.0f);
        unsigned bal1 = __ballot_sync(F, Wb != 0.0f);
        while (bal0) {
            int p = __ffs(bal0) - 1; bal0 &= bal0 - 1;
            float wv = __shfl_sync(F, Wa, p);
            const float* row = patch_values + p * H;
            #pragma unroll
            for (int j = 0; j < 6; j++) pacc[j] += wv * __ldg(row + lane + 32 * j);
        }
        while (bal1) {
            int p = __ffs(bal1) - 1; bal1 &= bal1 - 1;
            float wv = __shfl_sync(F, Wb, p);
            const float* row = patch_values + (p + 32) * H;
            #pragma unroll
            for (int j = 0; j < 6; j++) pacc[j] += wv * __ldg(row + lane + 32 * j);
        }
        #pragma unroll
        for (int j = 0; j < 6; j++) out_ps[(size_t)tg * H + lane + 32 * j] = pacc[j];

        if (lane == 0) {
            out_anchor[(size_t)tg * 3 + 0] = ax;
            out_anchor[(size_t)tg * 3 + 1] = ay;
            out_anchor[(size_t)tg * 3 + 2] = az;
            out_lm[tg]  = lm;
            out_bm[tg]  = bm;
            out_md[tg]  = md;
            out_rad[tg] = RAD;
            out_bs[tg]  = 0.18f;
        }
    }
}

// ---- pass 2: recompute flagged tokens. GEMV: 1 LDG.128/k-row (lane owns
//      n = 4*lane..4*lane+3), q broadcast via smem LDS, sequential-k fmaf
//      chain per output (identical accumulation order as before). ----
__global__ __launch_bounds__(256)
void fixup(const float* __restrict__ token_state,
           const float* __restrict__ prev_state,
           const float* __restrict__ b_sel,
           const float* __restrict__ b_br,
           const float* __restrict__ patch_values,
           const float* __restrict__ patch_positions,
           float* __restrict__ out_ps,
           float* __restrict__ out_w,
           float* __restrict__ out_anchor,
           float* __restrict__ out_lm,
           float* __restrict__ out_bm,
           float* __restrict__ out_md,
           float* __restrict__ out_rad,
           float* __restrict__ out_bs)
{
    __shared__ float sQ[8][384];
    __shared__ float sL[8][128];

    const unsigned F = 0xffffffffu;
    const int lane  = threadIdx.x & 31;
    const int w     = threadIdx.x >> 5;
    const int warpG = (blockIdx.x * blockDim.x + threadIdx.x) >> 5;
    const int nwarp = (gridDim.x * blockDim.x) >> 5;
    const int n = g_cnt;

    const float PXa = __ldg(&patch_positions[lane * 3 + 0]);
    const float PYa = __ldg(&patch_positions[lane * 3 + 1]);
    const float PZa = __ldg(&patch_positions[lane * 3 + 2]);
    const float PXb = __ldg(&patch_positions[(lane + 32) * 3 + 0]);
    const float PYb = __ldg(&patch_positions[(lane + 32) * 3 + 1]);
    const float PZb = __ldg(&patch_positions[(lane + 32) * 3 + 2]);
    const float RAD  = 0.42f;
    const float NEGK = -1.0f / (2.0f * 0.42f * 0.42f);

    // per-lane biases for owned columns n = 4*lane + i (hoisted: token-invariant)
    float bsv[4];
    #pragma unroll
    for (int i = 0; i < 4; i++) {
        int nn = 4 * lane + i;
        bsv[i] = (nn < 64) ? __ldg(b_sel + nn) : __ldg(b_br + nn - 64);
    }

    const float4* wt4 = (const float4*)g_wt;

    for (int i = warpG; i < n; i += nwarp) {
        const int tg = g_list[i];
        const float* q1 = token_state + (size_t)tg * H;
        const float* q2 = prev_state + (size_t)tg * H;

        #pragma unroll
        for (int j = 0; j < 6; j++) sQ[w][j * 32 + lane]       = __ldg(q1 + j * 32 + lane);
        #pragma unroll
        for (int j = 0; j < 6; j++) sQ[w][192 + j * 32 + lane] = __ldg(q2 + j * 32 + lane);
        __syncwarp();

        // 4 sequential-k fmaf chains (outputs n=4l..4l+3), k ascending 0..383
        float a0 = 0.f, a1 = 0.f, a2 = 0.f, a3 = 0.f;
        #pragma unroll 8
        for (int k = 0; k < 384; k++) {
            float q = sQ[w][k];
            float4 wv = __ldg(wt4 + k * 32 + lane);
            a0 = fmaf(q, wv.x, a0);
            a1 = fmaf(q, wv.y, a1);
            a2 = fmaf(q, wv.z, a2);
            a3 = fmaf(q, wv.w, a3);
        }
        sL[w][4 * lane + 0] = a0 + bsv[0];
        sL[w][4 * lane + 1] = a1 + bsv[1];
        sL[w][4 * lane + 2] = a2 + bsv[2];
        sL[w][4 * lane + 3] = a3 + bsv[3];
        __syncwarp();

        float ba = sL[w][lane],      bb = sL[w][lane + 32];
        float ga = sL[w][lane + 64], gb = sL[w][lane + 96];
        __syncwarp();

        float mx = fmaxf(ba, bb);
        #pragma unroll
        for (int o = 16; o; o >>= 1) mx = fmaxf(mx, __shfl_xor_sync(F, mx, o));
        float ea = expf(ba - mx), eb = expf(bb - mx);
        float s = ea + eb;
        #pragma unroll
        for (int o = 16; o; o >>= 1) s += __shfl_xor_sync(F, s, o);
        float inv = 1.0f / s;
        float wa = ea * inv, wb = eb * inv;

        float ax = wa * PXa + wb * PXb;
        float ay = wa * PYa + wb * PYb;
        float az = wa * PZa + wb * PZb;
        #pragma unroll
        for (int o = 16; o; o >>= 1) {
            ax += __shfl_xor_sync(F, ax, o);
            ay += __shfl_xor_sync(F, ay, o);
            az += __shfl_xor_sync(F, az, o);
        }

        float dxa = ax - PXa, dya = ay - PYa, dza = az - PZa;
        float dxb = ax - PXb, dyb = ay - PYb, dzb = az - PZb;
        float da = sqrtf(dxa * dxa + dya * dya + dza * dza);
        float db = sqrtf(dxb * dxb + dyb * dyb + dzb * dzb);
        float ka = expf(da * da * NEGK);
        float kb = expf(db * db * NEGK);
        bool la = (da <= RAD), lb = (db <= RAD);

        unsigned long long keya = (((unsigned long long)__float_as_uint(da)) << 32) | (unsigned)lane;
        unsigned long long keyb = (((unsigned long long)__float_as_uint(db)) << 32) | (unsigned)(lane + 32);
        unsigned long long kmin = keya < keyb ? keya : keyb;
        #pragma unroll
        for (int o = 16; o; o >>= 1) {
            unsigned long long ok = __shfl_xor_sync(F, kmin, o);
            if (ok < kmin) kmin = ok;
        }
        int nearest = (int)(kmin & 0x3fu);
        la = la || (lane == nearest);
        lb = lb || (lane + 32 == nearest);

        float va_ = la ? -1e9f : ga;
        float vb_ = lb ? -1e9f : gb;
        float tv[6]; int ti[6];
        #pragma unroll
        for (int j = 0; j < 6; j++) {
            float bv; int bi;
            if (va_ >= vb_) { bv = va_; bi = lane; } else { bv = vb_; bi = lane + 32; }
            #pragma unroll
            for (int o = 16; o; o >>= 1) {
                float ov = __shfl_xor_sync(F, bv, o);
                int   oi = __shfl_xor_sync(F, bi, o);
                if (ov > bv || (ov == bv && oi < bi)) { bv = ov; bi = oi; }
            }
            tv[j] = bv; ti[j] = bi;
            if (bi == lane)      va_ = -3.4e38f;
            if (bi == lane + 32) vb_ = -3.4e38f;
        }
        float s6 = 0.0f, e6[6];
        #pragma unroll
        for (int j = 0; j < 6; j++) { e6[j] = expf(tv[j] - tv[0]); s6 += e6[j]; }
        float is6 = 1.0f / s6;
        float sba = 0.0f, sbb = 0.0f;
        #pragma unroll
        for (int j = 0; j < 6; j++) {
            float v = e6[j] * is6;
            if (ti[j] == lane)      sba = v;
            if (ti[j] == lane + 32) sbb = v;
        }

        float fla = la ? 1.0f : 0.0f, flb = lb ? 1.0f : 0.0f;
        float ma = wa * ka * fla + 0.18f * sba;
        float mb = wb * kb * flb + 0.18f * sbb;
        float smx = ma + mb;
        #pragma unroll
        for (int o = 16; o; o >>= 1) smx += __shfl_xor_sync(F, smx, o);
        float invd = 1.0f / fmaxf(smx, 1e-6f);
        float Wa = ma * invd, Wb = mb * invd;

        out_w[(size_t)tg * PP + lane]      = Wa;
        out_w[(size_t)tg * PP + 32 + lane] = Wb;

        float lm = Wa * fla + Wb * flb;
        float bm = Wa * (1.0f - fla) + Wb * (1.0f - flb);
        float md = Wa * da + Wb * db;
        #pragma unroll
        for (int o = 16; o; o >>= 1) {
            lm += __shfl_xor_sync(F, lm, o);
            bm += __shfl_xor_sync(F, bm, o);
            md += __shfl_xor_sync(F, md, o);
        }

        float pacc[6] = {0, 0, 0, 0, 0, 0};
        unsigned bal0 = __ballot_sync(F, Wa != 0.0f);
        unsigned bal1 = __ballot_sync(F, Wb != 0.0f);
        while (bal0) {
            int p = __ffs(bal0) - 1; bal0 &= bal0 - 1;
            float wv = __shfl_sync(F, Wa, p);
            const float* row = patch_values + p * H;
            #pragma unroll
            for (int j = 0; j < 6; j++) pacc[j] += wv * __ldg(row + lane + 32 * j);
        }
        while (bal1) {
            int p = __ffs(bal1) - 1; bal1 &= bal1 - 1;
            float wv = __shfl_sync(F, Wb, p);
            const float* row = patch_values + (p + 32) * H;
            #pragma unroll
            for (int j = 0; j < 6; j++) pacc[j] += wv * __ldg(row + lane + 32 * j);
        }
        #pragma unroll
        for (int j = 0; j < 6; j++) out_ps[(size_t)tg * H + lane + 32 * j] = pacc[j];

        if (lane == 0) {
            out_anchor[(size_t)tg * 3 + 0] = ax;
            out_anchor[(size_t)tg * 3 + 1] = ay;
            out_anchor[(size_t)tg * 3 + 2] = az;
            out_lm[tg]  = lm;
            out_bm[tg]  = bm;
            out_md[tg]  = md;
            out_rad[tg] = RAD;
            out_bs[tg]  = 0.18f;
        }
    }
}

extern "C" void kernel_launch(void* const* d_in, const int* in_sizes, int n_in,
                              void* d_out, int out_size)
{
    const float* token_state     = (const float*)d_in[0];
    const float* prev_state      = (const float*)d_in[1];
    const float* W_sel           = (const float*)d_in[2];
    const float* b_sel           = (const float*)d_in[3];
    const float* W_br            = (const float*)d_in[4];
    const float* b_br            = (const float*)d_in[5];
    const float* patch_values    = (const float*)d_in[6];
    const float* patch_positions = (const float*)d_in[7];

    const int B = in_sizes[0] / H;
    float* o = (float*)d_out;
    float* out_ps     = o;
    float* out_w      = o + (size_t)B * H;
    float* out_anchor = o + (size_t)B * (H + PP);
    float* out_lm     = o + (size_t)B * (H + PP + 3);
    float* out_bm     = out_lm + B;
    float* out_md     = out_bm + B;
    float* out_rad    = out_md + B;
    float* out_bs     = out_rad + B;

    reset_cnt<<<1, 32>>>();
    prep_w<<<288, 256>>>(W_sel, W_br);   // 73728 work items

    const int smem_bytes = SMEM_FLOATS * sizeof(float); // 68864
    cudaFuncSetAttribute(taps_mma, cudaFuncAttributeMaxDynamicSharedMemorySize, smem_bytes);

    int grid = (B + 127) / 128;
    taps_mma<<<grid, 256, smem_bytes>>>(
        token_state, prev_state, b_sel, b_br,
        patch_values, patch_positions,
        out_ps, out_w, out_anchor, out_lm, out_bm, out_md, out_rad, out_bs, B);

    fixup<<<256, 256>>>(token_state, prev_state, b_sel, b_br,
                        patch_values, patch_positions,
                        out_ps, out_w, out_anchor, out_lm, out_bm, out_md,
                        out_rad, out_bs);
}